// round 15
// baseline (speedup 1.0000x reference)
#include <cuda_runtime.h>
#include <cfloat>
#include <cstdint>

#define BSZ   8
#define NPTS  2048
#define KNN   10
#define MBIG  (NPTS * KNN)   // 20480
#define OPAD  768            // padded O stride for transposed weights
#define CPAD  704            // padded C rows (704 = 44*16, covers 693)
#define KT    16             // GEMM k-tile depth
#define NSTG  3              // cp.async pipeline stages (48KB smem, keeps 2 CTA/SM)

typedef unsigned long long u64;
union F2U { float2 f2; u64 u; };

// ---------------- scratch (device globals; allocation-free) ----------------
__device__ float g_G   [(size_t)BSZ * NPTS * NPTS];     // gram
__device__ float g_sq  [BSZ * NPTS];
__device__ int   g_idx [BSZ * NPTS * KNN];
__device__ float g_feat[(size_t)BSZ * 362 * MBIG];      // edge features (block 1)
__device__ float g_y1  [(size_t)BSZ * 430 * MBIG];      // conv1 out (max O=430)
__device__ float g_y2  [(size_t)BSZ * 512 * MBIG];      // conv2 out (max O=512)
__device__ float g_x1  [BSZ * 181 * NPTS];
__device__ float g_x2  [BSZ * 512 * NPTS];
__device__ float g_y3  [BSZ * 595 * NPTS];
__device__ float g_P   [BSZ * 430 * NPTS];              // split-conv P
__device__ float g_S   [BSZ * 430 * NPTS];              // split-conv S (incl bias)
__device__ float g_wt  [CPAD * OPAD];                   // transposed + padded weights
__device__ double g_p1 [512 * BSZ];                     // stats partials (sum)
__device__ double g_p2 [512 * BSZ];                     // stats partials (sumsq)
__device__ float g_mean[1024];
__device__ float g_var [1024];

// ---- squared norms: XLA row-reduction emulation (BIT-FROZEN, feeds knn) ----
__global__ void sqnorm_warp_k(const float* __restrict__ X, float* __restrict__ sq, int C)
{
    int gw   = (blockIdx.x * blockDim.x + threadIdx.x) >> 5;
    int lane = threadIdx.x & 31;
    if (gw >= BSZ * NPTS) return;
    int b = gw / NPTS, n = gw % NPTS;
    const float* Xb = X + (size_t)b * C * NPTS + n;
    float s = 0.f;
    for (int c = lane; c < C; c += 32) {
        float v = Xb[(size_t)c * NPTS];
        s = __fadd_rn(s, __fmul_rn(v, v));
    }
    #pragma unroll
    for (int off = 16; off > 0; off >>= 1)
        s = __fadd_rn(s, __shfl_down_sync(0xffffffffu, s, off));
    if (lane == 0) sq[gw] = s;
}

// --------- W transpose (sub-slice, strided) into padded buffer ----------
__global__ void transw_k(const float* __restrict__ W, float* __restrict__ Wt,
                         int O, int C, int ldW, int coff)
{
    int i = blockIdx.x * blockDim.x + threadIdx.x;
    int ctot = (C + KT - 1) & ~(KT - 1);
    if (i >= ctot * OPAD) return;
    int c = i / OPAD, o = i % OPAD;
    Wt[i] = (c < C && o < O) ? W[(size_t)o * ldW + coff + c] : 0.f;
}

// Wt[c][o] = W[o*ldW + coff2 + c] - W[o*ldW + coff1 + c]
__global__ void transw_diff_k(const float* __restrict__ W, float* __restrict__ Wt,
                              int O, int C, int ldW, int coff1, int coff2)
{
    int i = blockIdx.x * blockDim.x + threadIdx.x;
    int ctot = (C + KT - 1) & ~(KT - 1);
    if (i >= ctot * OPAD) return;
    int c = i / OPAD, o = i % OPAD;
    Wt[i] = (c < C && o < O)
          ? W[(size_t)o * ldW + coff2 + c] - W[(size_t)o * ldW + coff1 + c] : 0.f;
}

// ---------------- cp.async helpers ----------------
__device__ __forceinline__ void cpa16(uint32_t s, const void* g, int sz)
{
    asm volatile("cp.async.cg.shared.global [%0], [%1], 16, %2;"
                 :: "r"(s), "l"(g), "r"(sz));
}
__device__ __forceinline__ void cpa_commit() { asm volatile("cp.async.commit_group;"); }
template<int N> __device__ __forceinline__ void cpa_wait()
{ asm volatile("cp.async.wait_group %0;" :: "n"(N)); }

// packed dual fp32 FMA (each half IEEE RN, same rounding as scalar FFMA)
__device__ __forceinline__ void ffma2(u64& d, u64 a, u64 b)
{
    asm("fma.rn.f32x2 %0, %1, %2, %0;" : "+l"(d) : "l"(a), "l"(b));
}
__device__ __forceinline__ u64 packdup(float a)
{
    u64 r;
    asm("mov.b64 %0, {%1, %1};" : "=l"(r) : "f"(a));
    return r;
}

// ------- 3-stage pipelined 128x128xKT SIMT sgemm, FFMA2 inner ---------------
// Per-output accumulation: single register chain, fmaf, strictly ascending c
// (bit-identical to all prior passing gemms; only the staging ring deepens).
__global__ __launch_bounds__(256, 2) void gemm_db_k(
    const float* __restrict__ A, const float* __restrict__ X,
    const float* __restrict__ bias, float* __restrict__ Y,
    int O, int C, int M, int ldA, size_t sA, size_t sX, size_t sY)
{
    const int b = blockIdx.z;
    const float* Ab = A + (size_t)b * sA;
    const float* Xb = X + (size_t)b * sX;
    float* Yb = Y + (size_t)b * sY;
    const int m0 = blockIdx.x * 128;
    const int o0 = blockIdx.y * 128;
    const int tid = threadIdx.x;
    const int tx = tid & 15, ty = tid >> 4;

    __shared__ float As[NSTG][KT][128];
    __shared__ float Bs[NSTG][KT][128];

    const int rr = tid >> 4;
    const int cl = (tid & 15) * 8;

    uint32_t saA = (uint32_t)__cvta_generic_to_shared(&As[0][rr][cl]);
    uint32_t saB = (uint32_t)__cvta_generic_to_shared(&Bs[0][rr][cl]);
    const uint32_t bufoff = KT * 128 * 4;

    const int ntiles = (C + KT - 1) / KT;

    u64 acc2[2][2][4][2];
    #pragma unroll
    for (int rh = 0; rh < 2; rh++)
        #pragma unroll
        for (int ch = 0; ch < 2; ch++)
            #pragma unroll
            for (int i = 0; i < 4; i++)
                { acc2[rh][ch][i][0] = 0ull; acc2[rh][ch][i][1] = 0ull; }

    // prologue: prefetch tiles 0 and 1
    #pragma unroll
    for (int p = 0; p < 2; p++) {
        if (p < ntiles) {
            int c = p * KT + rr;
            int pz = (c < C) ? 16 : 0;
            int cs = (c < C) ? c : 0;
            uint32_t nb = (uint32_t)p * bufoff;
            const float* ga = Ab + (size_t)cs * ldA + o0 + cl;
            const float* gx = Xb + (size_t)cs * M + m0 + cl;
            cpa16(saA + nb,      ga,     pz);
            cpa16(saA + nb + 16, ga + 4, pz);
            cpa16(saB + nb,      gx,     pz);
            cpa16(saB + nb + 16, gx + 4, pz);
            cpa_commit();
        }
    }

    int stg = 0;
    for (int it = 0; it < ntiles; it++) {
        if (it + 2 < ntiles) {
            int c = (it + 2) * KT + rr;
            int pz = (c < C) ? 16 : 0;
            int cs = (c < C) ? c : 0;
            int ps = (it + 2) % NSTG;
            uint32_t nb = (uint32_t)ps * bufoff;
            const float* ga = Ab + (size_t)cs * ldA + o0 + cl;
            const float* gx = Xb + (size_t)cs * M + m0 + cl;
            cpa16(saA + nb,      ga,     pz);
            cpa16(saA + nb + 16, ga + 4, pz);
            cpa16(saB + nb,      gx,     pz);
            cpa16(saB + nb + 16, gx + 4, pz);
            cpa_commit();
            cpa_wait<2>();
        } else if (it + 1 < ntiles) {
            cpa_wait<1>();
        } else {
            cpa_wait<0>();
        }
        __syncthreads();
        const int buf = stg;
        #pragma unroll
        for (int k = 0; k < KT; k++) {
            float a[2][4];
            *(float4*)a[0] = *(const float4*)&As[buf][k][ty * 4];
            *(float4*)a[1] = *(const float4*)&As[buf][k][64 + ty * 4];
            u64 x0[2], x1[2];
            {
                ulonglong2 v = *(const ulonglong2*)&Bs[buf][k][tx * 4];
                x0[0] = v.x; x0[1] = v.y;
            }
            {
                ulonglong2 v = *(const ulonglong2*)&Bs[buf][k][64 + tx * 4];
                x1[0] = v.x; x1[1] = v.y;
            }
            #pragma unroll
            for (int rh = 0; rh < 2; rh++)
                #pragma unroll
                for (int i = 0; i < 4; i++) {
                    u64 aa = packdup(a[rh][i]);
                    ffma2(acc2[rh][0][i][0], aa, x0[0]);
                    ffma2(acc2[rh][0][i][1], aa, x0[1]);
                    ffma2(acc2[rh][1][i][0], aa, x1[0]);
                    ffma2(acc2[rh][1][i][1], aa, x1[1]);
                }
        }
        __syncthreads();
        stg = (stg + 1 == NSTG) ? 0 : stg + 1;
    }

    #pragma unroll
    for (int rh = 0; rh < 2; rh++)
        #pragma unroll
        for (int i = 0; i < 4; i++) {
            int o = o0 + rh * 64 + ty * 4 + i;
            if (o < O) {
                #pragma unroll
                for (int ch = 0; ch < 2; ch++) {
                    F2U q0, q1;
                    q0.u = acc2[rh][ch][i][0];
                    q1.u = acc2[rh][ch][i][1];
                    float4 r;
                    if (bias) {
                        float bv = bias[o];
                        r.x = q0.f2.x + bv; r.y = q0.f2.y + bv;
                        r.z = q1.f2.x + bv; r.w = q1.f2.y + bv;
                    } else {
                        r.x = q0.f2.x; r.y = q0.f2.y;
                        r.z = q1.f2.x; r.w = q1.f2.y;
                    }
                    *(float4*)&Yb[(size_t)o * M + m0 + ch * 64 + tx * 4] = r;
                }
            }
        }
}

// ------- dual-source variant: rows [0,Csplit) from X, rows >= Csplit from X2 --
__global__ __launch_bounds__(256, 2) void gemm_db_dual_k(
    const float* __restrict__ A, const float* __restrict__ X,
    const float* __restrict__ X2, int Csplit,
    const float* __restrict__ bias, float* __restrict__ Y,
    int O, int C, int M, int ldA, size_t sA, size_t sX, size_t sX2, size_t sY)
{
    const int b = blockIdx.z;
    const float* Ab  = A  + (size_t)b * sA;
    const float* Xb  = X  + (size_t)b * sX;
    const float* X2b = X2 + (size_t)b * sX2;
    float* Yb = Y + (size_t)b * sY;
    const int m0 = blockIdx.x * 128;
    const int o0 = blockIdx.y * 128;
    const int tid = threadIdx.x;
    const int tx = tid & 15, ty = tid >> 4;

    __shared__ float As[NSTG][KT][128];
    __shared__ float Bs[NSTG][KT][128];

    const int rr = tid >> 4;
    const int cl = (tid & 15) * 8;

    uint32_t saA = (uint32_t)__cvta_generic_to_shared(&As[0][rr][cl]);
    uint32_t saB = (uint32_t)__cvta_generic_to_shared(&Bs[0][rr][cl]);
    const uint32_t bufoff = KT * 128 * 4;

    const int ntiles = (C + KT - 1) / KT;

    u64 acc2[2][2][4][2];
    #pragma unroll
    for (int rh = 0; rh < 2; rh++)
        #pragma unroll
        for (int ch = 0; ch < 2; ch++)
            #pragma unroll
            for (int i = 0; i < 4; i++)
                { acc2[rh][ch][i][0] = 0ull; acc2[rh][ch][i][1] = 0ull; }

    #pragma unroll
    for (int p = 0; p < 2; p++) {
        if (p < ntiles) {
            int c = p * KT + rr;
            int pz = (c < C) ? 16 : 0;
            int cs = (c < C) ? c : 0;
            uint32_t nb = (uint32_t)p * bufoff;
            const float* ga = Ab + (size_t)cs * ldA + o0 + cl;
            const float* gx = (cs < Csplit) ? Xb + (size_t)cs * M + m0 + cl
                                            : X2b + (size_t)(cs - Csplit) * M + m0 + cl;
            cpa16(saA + nb,      ga,     pz);
            cpa16(saA + nb + 16, ga + 4, pz);
            cpa16(saB + nb,      gx,     pz);
            cpa16(saB + nb + 16, gx + 4, pz);
            cpa_commit();
        }
    }

    int stg = 0;
    for (int it = 0; it < ntiles; it++) {
        if (it + 2 < ntiles) {
            int c = (it + 2) * KT + rr;
            int pz = (c < C) ? 16 : 0;
            int cs = (c < C) ? c : 0;
            int ps = (it + 2) % NSTG;
            uint32_t nb = (uint32_t)ps * bufoff;
            const float* ga = Ab + (size_t)cs * ldA + o0 + cl;
            const float* gx = (cs < Csplit) ? Xb + (size_t)cs * M + m0 + cl
                                            : X2b + (size_t)(cs - Csplit) * M + m0 + cl;
            cpa16(saA + nb,      ga,     pz);
            cpa16(saA + nb + 16, ga + 4, pz);
            cpa16(saB + nb,      gx,     pz);
            cpa16(saB + nb + 16, gx + 4, pz);
            cpa_commit();
            cpa_wait<2>();
        } else if (it + 1 < ntiles) {
            cpa_wait<1>();
        } else {
            cpa_wait<0>();
        }
        __syncthreads();
        const int buf = stg;
        #pragma unroll
        for (int k = 0; k < KT; k++) {
            float a[2][4];
            *(float4*)a[0] = *(const float4*)&As[buf][k][ty * 4];
            *(float4*)a[1] = *(const float4*)&As[buf][k][64 + ty * 4];
            u64 x0[2], x1[2];
            {
                ulonglong2 v = *(const ulonglong2*)&Bs[buf][k][tx * 4];
                x0[0] = v.x; x0[1] = v.y;
            }
            {
                ulonglong2 v = *(const ulonglong2*)&Bs[buf][k][64 + tx * 4];
                x1[0] = v.x; x1[1] = v.y;
            }
            #pragma unroll
            for (int rh = 0; rh < 2; rh++)
                #pragma unroll
                for (int i = 0; i < 4; i++) {
                    u64 aa = packdup(a[rh][i]);
                    ffma2(acc2[rh][0][i][0], aa, x0[0]);
                    ffma2(acc2[rh][0][i][1], aa, x0[1]);
                    ffma2(acc2[rh][1][i][0], aa, x1[0]);
                    ffma2(acc2[rh][1][i][1], aa, x1[1]);
                }
        }
        __syncthreads();
        stg = (stg + 1 == NSTG) ? 0 : stg + 1;
    }

    #pragma unroll
    for (int rh = 0; rh < 2; rh++)
        #pragma unroll
        for (int i = 0; i < 4; i++) {
            int o = o0 + rh * 64 + ty * 4 + i;
            if (o < O) {
                #pragma unroll
                for (int ch = 0; ch < 2; ch++) {
                    F2U q0, q1;
                    q0.u = acc2[rh][ch][i][0];
                    q1.u = acc2[rh][ch][i][1];
                    float4 r;
                    if (bias) {
                        float bv = bias[o];
                        r.x = q0.f2.x + bv; r.y = q0.f2.y + bv;
                        r.z = q1.f2.x + bv; r.w = q1.f2.y + bv;
                    } else {
                        r.x = q0.f2.x; r.y = q0.f2.y;
                        r.z = q1.f2.x; r.w = q1.f2.y;
                    }
                    *(float4*)&Yb[(size_t)o * M + m0 + ch * 64 + tx * 4] = r;
                }
            }
        }
}

// ------- top-10: register-resident keys (round-10 best-known version) --------
__global__ void topk_k(const float* __restrict__ G, const float* __restrict__ sq,
                       int* __restrict__ idx)
{
    const int n = blockIdx.x, b = blockIdx.y;
    const float* Gr  = G + ((size_t)b * NPTS + n) * NPTS;
    const float* sqb = sq + b * NPTS;
    const int t = threadIdx.x;
    const int lane = t & 31, warp = t >> 5;
    const float sqn = sqb[n];

    float key[8];
    #pragma unroll
    for (int s = 0; s < 8; s++) {
        int j = s * 256 + t;
        key[s] = (j == n) ? FLT_MAX
               : __fadd_rn(__fadd_rn(__fmul_rn(-2.f, Gr[j]), sqb[j]), sqn);
    }

    __shared__ float swv[8];
    __shared__ int   swi[8];
    __shared__ int   win;

    for (int r = 0; r < KNN; r++) {
        float bv = key[0]; int bs = 0;
        #pragma unroll
        for (int s = 1; s < 8; s++)
            if (key[s] < bv) { bv = key[s]; bs = s; }
        int bj = bs * 256 + t;
        #pragma unroll
        for (int off = 16; off > 0; off >>= 1) {
            float ov = __shfl_down_sync(0xffffffffu, bv, off);
            int   oj = __shfl_down_sync(0xffffffffu, bj, off);
            if (ov < bv || (ov == bv && oj < bj)) { bv = ov; bj = oj; }
        }
        if (lane == 0) { swv[warp] = bv; swi[warp] = bj; }
        __syncthreads();
        if (t == 0) {
            float fv = swv[0]; int fj = swi[0];
            #pragma unroll
            for (int w = 1; w < 8; w++)
                if (swv[w] < fv || (swv[w] == fv && swi[w] < fj)) { fv = swv[w]; fj = swi[w]; }
            idx[((size_t)b * NPTS + n) * KNN + r] = fj;
            win = fj;
        }
        __syncthreads();
        int fj = win;
        if ((fj & 255) == t) key[fj >> 8] = FLT_MAX;
        __syncthreads();
    }
}

// ---------------- gather edge features (block 1 only, FROZEN path) ----------
__global__ void gather_k(const float* __restrict__ X, const int* __restrict__ idx,
                         float* __restrict__ F, int C)
{
    size_t total = (size_t)BSZ * 2 * C * MBIG;
    size_t i = (size_t)blockIdx.x * blockDim.x + threadIdx.x;
    if (i >= total) return;
    int m = (int)(i % MBIG);
    size_t r = i / MBIG;
    int c = (int)(r % (2 * C));
    int b = (int)(r / (2 * C));
    int n = m / KNN, k = m % KNN;
    if (c < C) {
        int j = idx[((size_t)b * NPTS + n) * KNN + k];
        const float* row = X + ((size_t)b * C + c) * NPTS;
        F[i] = row[j] - row[n];
    } else {
        F[i] = X[((size_t)b * C + (c - C)) * NPTS + n];
    }
}

// --- analytic BN1 stats for block2, stage 1: per-(o,b) partials -------------
__global__ void stats_ps_part_k(const float* __restrict__ P, const float* __restrict__ S,
                                const int* __restrict__ idx,
                                double* __restrict__ p1, double* __restrict__ p2, int O)
{
    const int o = blockIdx.x;
    const int b = blockIdx.y;
    const int t = threadIdx.x;
    __shared__ float prow[NPTS];
    __shared__ double r1[256], r2[256];
    const float* Pb = P + ((size_t)b * O + o) * NPTS;
    const float* Sb = S + ((size_t)b * O + o) * NPTS;
    const int*   ib = idx + (size_t)b * MBIG;
    for (int j = t; j < NPTS; j += 256) prow[j] = Pb[j];
    __syncthreads();
    double s1 = 0.0, s2 = 0.0;
    for (int n = t; n < NPTS; n += 256) {
        float sv = Sb[n];
        const int* ii = ib + n * KNN;
        float ts = 0.f, us = 0.f;
        #pragma unroll
        for (int k = 0; k < KNN; k++) {
            float p = prow[ii[k]];
            ts += p;
            us = fmaf(p, p, us);
        }
        s1 += (double)(ts + 10.f * sv);
        s2 += (double)(us + 2.f * sv * ts + 10.f * sv * sv);
    }
    r1[t] = s1; r2[t] = s2;
    __syncthreads();
    for (int w = 128; w > 0; w >>= 1) {
        if (t < w) { r1[t] += r1[t + w]; r2[t] += r2[t + w]; }
        __syncthreads();
    }
    if (t == 0) { p1[o * BSZ + b] = r1[0]; p2[o * BSZ + b] = r2[0]; }
}

// --- stage 2: deterministic finalize (ascending b) -> BN affine a/bb --------
__global__ void stats_ps_final_k(const double* __restrict__ p1, const double* __restrict__ p2,
                                 const float* __restrict__ gam, const float* __restrict__ bet,
                                 float* __restrict__ Aout, float* __restrict__ BBout, int O)
{
    int o = blockIdx.x * blockDim.x + threadIdx.x;
    if (o >= O) return;
    double s1 = 0.0, s2 = 0.0;
    #pragma unroll
    for (int b = 0; b < BSZ; b++) { s1 += p1[o * BSZ + b]; s2 += p2[o * BSZ + b]; }
    double inv = 1.0 / ((double)BSZ * (double)MBIG);
    double mu  = s1 * inv;
    double var = s2 * inv - mu * mu;
    if (var < 0.0) var = 0.0;
    float a  = rsqrtf((float)var + 1e-5f) * gam[o];
    float bb = bet[o] - (float)mu * a;
    Aout[o]  = a;
    BBout[o] = bb;
}

// -------- combine + BN affine + leaky: Y1 = leaky(a*(P[idx]+S) + bb) --------
__global__ void combine_bn_k(const float* __restrict__ P, const float* __restrict__ S,
                             const int* __restrict__ idx,
                             const float* __restrict__ A, const float* __restrict__ BB,
                             float* __restrict__ Y, int O)
{
    size_t total = (size_t)BSZ * O * MBIG;
    size_t i = (size_t)blockIdx.x * blockDim.x + threadIdx.x;
    if (i >= total) return;
    int m = (int)(i % MBIG);
    size_t r = i / MBIG;
    int o = (int)(r % O);
    int b = (int)(r / O);
    int n = m / KNN;
    int j = idx[(size_t)b * MBIG + m];
    size_t base = ((size_t)b * O + o) * NPTS;
    float v = fmaf(P[base + j] + S[base + n], A[o], BB[o]);
    Y[i] = (v >= 0.f) ? v : 0.2f * v;
}

// ------- BN statistics, two-pass (BIT-FROZEN: block-1 stats feed knn-2) ------
__global__ void bn_stats_k(const float* __restrict__ Y, float* __restrict__ mean,
                           float* __restrict__ var, int O, int M)
{
    const int c = blockIdx.x;
    const int t = threadIdx.x;
    __shared__ float ss[256];
    __shared__ float mu_s;
    float s = 0.f;
    for (int b = 0; b < BSZ; b++) {
        const float* p = Y + ((size_t)b * O + c) * M;
        for (int m = t; m < M; m += 256) s += p[m];
    }
    ss[t] = s;
    __syncthreads();
    for (int w = 128; w > 0; w >>= 1) {
        if (t < w) ss[t] += ss[t + w];
        __syncthreads();
    }
    if (t == 0) {
        float mu = ss[0] / ((float)BSZ * (float)M);
        mean[c] = mu;
        mu_s = mu;
    }
    __syncthreads();
    const float mu = mu_s;
    float s2 = 0.f;
    for (int b = 0; b < BSZ; b++) {
        const float* p = Y + ((size_t)b * O + c) * M;
        for (int m = t; m < M; m += 256) { float d = p[m] - mu; s2 += d * d; }
    }
    ss[t] = s2;
    __syncthreads();
    for (int w = 128; w > 0; w >>= 1) {
        if (t < w) ss[t] += ss[t + w];
        __syncthreads();
    }
    if (t == 0) var[c] = ss[0] / ((float)BSZ * (float)M);
}

// ------- BN statistics, single-pass (tolerance paths) ----------
__global__ void bn_stats_fast_k(const float* __restrict__ Y, float* __restrict__ mean,
                                float* __restrict__ var, int O, int M)
{
    const int c = blockIdx.x;
    const int t = threadIdx.x;
    __shared__ float ss[256], ss2[256];
    float s = 0.f, s2 = 0.f;
    for (int b = 0; b < BSZ; b++) {
        const float* p = Y + ((size_t)b * O + c) * M;
        for (int m = t * 4; m < M; m += 1024) {
            float4 v = *(const float4*)(p + m);
            s += v.x; s2 = fmaf(v.x, v.x, s2);
            s += v.y; s2 = fmaf(v.y, v.y, s2);
            s += v.z; s2 = fmaf(v.z, v.z, s2);
            s += v.w; s2 = fmaf(v.w, v.w, s2);
        }
    }
    ss[t] = s; ss2[t] = s2;
    __syncthreads();
    for (int w = 128; w > 0; w >>= 1) {
        if (t < w) { ss[t] += ss[t + w]; ss2[t] += ss2[t + w]; }
        __syncthreads();
    }
    if (t == 0) {
        float inv = 1.f / ((float)BSZ * (float)M);
        float mu  = ss[0] * inv;
        mean[c] = mu;
        var[c]  = fmaxf(ss2[0] * inv - mu * mu, 0.f);
    }
}

// -------- apply BN affine + leaky relu, in place ----
__global__ void bn_leaky_k(float* __restrict__ Y, const float* __restrict__ mean,
                           const float* __restrict__ var, const float* __restrict__ gam,
                           const float* __restrict__ bet, int O, size_t M)
{
    size_t total = (size_t)BSZ * O * M;
    size_t i = ((size_t)blockIdx.x * blockDim.x + threadIdx.x) * 4;
    if (i >= total) return;
    int c = (int)((i / M) % O);
    float a  = rsqrtf(var[c] + 1e-5f) * gam[c];
    float bb = bet[c] - mean[c] * a;
    float4 v = *(float4*)(Y + i);
    float tt;
    tt = fmaf(v.x, a, bb); v.x = (tt >= 0.f) ? tt : 0.2f * tt;
    tt = fmaf(v.y, a, bb); v.y = (tt >= 0.f) ? tt : 0.2f * tt;
    tt = fmaf(v.z, a, bb); v.z = (tt >= 0.f) ? tt : 0.2f * tt;
    tt = fmaf(v.w, a, bb); v.w = (tt >= 0.f) ? tt : 0.2f * tt;
    *(float4*)(Y + i) = v;
}

// ---- BN + leaky + max over K, exact ref op order (BIT-FROZEN) ----
__global__ void bn_leaky_maxk_k(const float* __restrict__ Y, const float* __restrict__ mean,
                                const float* __restrict__ var, const float* __restrict__ gam,
                                const float* __restrict__ bet, float* __restrict__ out, int O)
{
    size_t total = (size_t)BSZ * O * NPTS;
    size_t i = (size_t)blockIdx.x * blockDim.x + threadIdx.x;
    if (i >= total) return;
    int n = (int)(i % NPTS);
    int c = (int)((i / NPTS) % O);
    int b = (int)(i / ((size_t)NPTS * O));
    const float mu = mean[c];
    const float s  = __fsqrt_rn(__fadd_rn(var[c], 1e-5f));
    const float g  = gam[c];
    const float be = bet[c];
    const float* p = Y + ((size_t)b * O + c) * MBIG + (size_t)n * KNN;
    float sel = p[0];
    if (g >= 0.f) {
        #pragma unroll
        for (int k = 1; k < KNN; k++) sel = fmaxf(sel, p[k]);
    } else {
        #pragma unroll
        for (int k = 1; k < KNN; k++) sel = fminf(sel, p[k]);
    }
    float t = __fdiv_rn(__fsub_rn(sel, mu), s);
    t = __fadd_rn(__fmul_rn(t, g), be);
    t = (t >= 0.f) ? t : __fmul_rn(0.2f, t);
    out[i] = t;
}

// ============================ host launcher ============================
static inline void* symaddr(const void* sym)
{
    void* p = nullptr;
    cudaGetSymbolAddress(&p, sym);
    return p;
}

extern "C" void kernel_launch(void* const* d_in, const int* in_sizes, int n_in,
                              void* d_out, int out_size)
{
    (void)in_sizes; (void)n_in; (void)out_size;
    const float* x = (const float*)d_in[0];

    const float* P24[24];
    for (int i = 0; i < 24; i++) P24[i] = (const float*)d_in[1 + i];
    #define W1(p)  P24[(p)*8 + 0]
    #define B1(p)  P24[(p)*8 + 1]
    #define G1(p)  P24[(p)*8 + 2]
    #define BE1(p) P24[(p)*8 + 3]
    #define W2(p)  P24[(p)*8 + 4]
    #define B2(p)  P24[(p)*8 + 5]
    #define G2(p)  P24[(p)*8 + 6]
    #define BE2(p) P24[(p)*8 + 7]

    float* G    = (float*)symaddr(g_G);
    float* SQ   = (float*)symaddr(g_sq);
    int*   IDX  = (int*)  symaddr(g_idx);
    float* FEAT = (float*)symaddr(g_feat);
    float* Y1   = (float*)symaddr(g_y1);
    float* Y2   = (float*)symaddr(g_y2);
    float* X1   = (float*)symaddr(g_x1);
    float* X2   = (float*)symaddr(g_x2);
    float* Y3   = (float*)symaddr(g_y3);
    float* PP   = (float*)symaddr(g_P);
    float* SS   = (float*)symaddr(g_S);
    float* WT   = (float*)symaddr(g_wt);
    double* P1  = (double*)symaddr(g_p1);
    double* P2  = (double*)symaddr(g_p2);
    float* MEAN = (float*)symaddr(g_mean);
    float* VAR  = (float*)symaddr(g_var);
    float* OUT  = (float*)d_out;

    const int ew = 256;
    #define GS(total) (unsigned)(((total) + ew - 1) / ew)
    #define CT(C) (((C) + KT - 1) & ~(KT - 1))

    auto conv = [&](const float* W, const float* bias, const float* Xin, float* Yout,
                    int O, int C, int M) {
        transw_k<<<GS(CT(C) * OPAD), ew>>>(W, WT, O, C, C, 0);
        gemm_db_k<<<dim3(M / 128, (O + 127) / 128, BSZ), 256>>>(
            WT, Xin, bias, Yout, O, C, M, OPAD, 0, (size_t)C * M, (size_t)O * M);
    };

    auto knn = [&](const float* xin, int C) {
        sqnorm_warp_k<<<(BSZ * NPTS * 32 + 255) / 256, 256>>>(xin, SQ, C);
        gemm_db_k<<<dim3(NPTS / 128, NPTS / 128, BSZ), 256>>>(
            xin, xin, nullptr, G, NPTS, C, NPTS,
            NPTS, (size_t)C * NPTS, (size_t)C * NPTS, (size_t)NPTS * NPTS);
        topk_k<<<dim3(NPTS, BSZ), 256>>>(G, SQ, IDX);
    };

    // ================= block 1 (FROZEN path: produces x1 -> knn-2) ============
    {
        const int C = 64, O1 = 152, O2 = 181;
        knn(x, C);
        gather_k<<<GS((size_t)BSZ * 2 * C * MBIG), ew>>>(x, IDX, FEAT, C);
        conv(W1(0), B1(0), FEAT, Y1, O1, 2 * C, MBIG);
        bn_stats_k<<<O1, 256>>>(Y1, MEAN, VAR, O1, MBIG);
        bn_leaky_k<<<GS((size_t)BSZ * O1 * MBIG / 4), ew>>>(Y1, MEAN, VAR, G1(0), BE1(0), O1, MBIG);
        conv(W2(0), B2(0), Y1, Y2, O2, O1, MBIG);
        bn_stats_k<<<O2, 256>>>(Y2, MEAN, VAR, O2, MBIG);
        bn_leaky_maxk_k<<<GS((size_t)BSZ * O2 * NPTS), ew>>>(Y2, MEAN, VAR, G2(0), BE2(0), X1, O2);
    }

    // ====== block 2 (tolerance path: split conv1 + parallel analytic stats) ==
    {
        const int C = 181, O1 = 430, O2 = 512;
        knn(X1, C);
        transw_k<<<GS(CT(C) * OPAD), ew>>>(W1(1), WT, O1, C, 2 * C, 0);
        gemm_db_k<<<dim3(NPTS / 128, (O1 + 127) / 128, BSZ), 256>>>(
            WT, X1, nullptr, PP, O1, C, NPTS, OPAD, 0, (size_t)C * NPTS, (size_t)O1 * NPTS);
        transw_diff_k<<<GS(CT(C) * OPAD), ew>>>(W1(1), WT, O1, C, 2 * C, 0, C);
        gemm_db_k<<<dim3(NPTS / 128, (O1 + 127) / 128, BSZ), 256>>>(
            WT, X1, B1(1), SS, O1, C, NPTS, OPAD, 0, (size_t)C * NPTS, (size_t)O1 * NPTS);
        stats_ps_part_k<<<dim3(O1, BSZ), 256>>>(PP, SS, IDX, P1, P2, O1);
        stats_ps_final_k<<<(O1 + 255) / 256, 256>>>(P1, P2, G1(1), BE1(1), MEAN, VAR, O1);
        combine_bn_k<<<GS((size_t)BSZ * O1 * MBIG), ew>>>(PP, SS, IDX, MEAN, VAR, Y1, O1);
        conv(W2(1), B2(1), Y1, Y2, O2, O1, MBIG);
        bn_stats_fast_k<<<O2, 256>>>(Y2, MEAN, VAR, O2, MBIG);
        bn_leaky_maxk_k<<<GS((size_t)BSZ * O2 * NPTS), ew>>>(Y2, MEAN, VAR, G2(1), BE2(1), X2, O2);
    }

    // ====== block 3 (tolerance path; concat fused into dual-source GEMM) =====
    {
        const int C = 693, Csplit = 181, O1 = 595, O2 = 512;
        transw_k<<<GS(CT(C) * OPAD), ew>>>(W1(2), WT, O1, C, C, 0);
        gemm_db_dual_k<<<dim3(NPTS / 128, (O1 + 127) / 128, BSZ), 256>>>(
            WT, X1, X2, Csplit, B1(2), Y3, O1, C, NPTS, OPAD,
            0, (size_t)Csplit * NPTS, (size_t)512 * NPTS, (size_t)O1 * NPTS);
        bn_stats_fast_k<<<O1, 256>>>(Y3, MEAN, VAR, O1, NPTS);
        bn_leaky_k<<<GS((size_t)BSZ * O1 * NPTS / 4), ew>>>(Y3, MEAN, VAR, G1(2), BE1(2), O1, NPTS);
        conv(W2(2), B2(2), Y3, OUT, O2, O1, NPTS);
        bn_stats_fast_k<<<O2, 256>>>(OUT, MEAN, VAR, O2, NPTS);
        bn_leaky_k<<<GS((size_t)BSZ * O2 * NPTS / 4), ew>>>(OUT, MEAN, VAR, G2(2), BE2(2), O2, NPTS);
    }
}

// round 16
// speedup vs baseline: 1.0394x; 1.0394x over previous
#include <cuda_runtime.h>
#include <cfloat>
#include <cstdint>

#define BSZ   8
#define NPTS  2048
#define KNN   10
#define MBIG  (NPTS * KNN)   // 20480
#define OPAD  768            // padded O stride for transposed weights
#define CPAD  704            // padded C rows (704 = 44*16, covers 693)
#define KT    16             // GEMM k-tile depth

typedef unsigned long long u64;
union F2U { float2 f2; u64 u; };

// ---------------- scratch (device globals; allocation-free) ----------------
__device__ float g_G   [(size_t)BSZ * NPTS * NPTS];     // gram
__device__ float g_sq  [BSZ * NPTS];
__device__ int   g_idx [BSZ * NPTS * KNN];
__device__ float g_feat[(size_t)BSZ * 362 * MBIG];      // edge features (block 1)
__device__ float g_y1  [(size_t)BSZ * 430 * MBIG];      // conv1 out (max O=430)
__device__ float g_y2  [(size_t)BSZ * 512 * MBIG];      // conv2 out (max O=512)
__device__ float g_x1  [BSZ * 181 * NPTS];
__device__ float g_x2  [BSZ * 512 * NPTS];
__device__ float g_y3  [BSZ * 595 * NPTS];
__device__ float g_P   [BSZ * 430 * NPTS];              // split-conv P
__device__ float g_S   [BSZ * 430 * NPTS];              // split-conv S (incl bias)
__device__ float g_wt  [CPAD * OPAD];                   // transposed + padded weights
__device__ double g_p1 [512 * BSZ];                     // stats partials (sum)
__device__ double g_p2 [512 * BSZ];                     // stats partials (sumsq)
__device__ float g_mean[1024];
__device__ float g_var [1024];

// ---- squared norms: XLA row-reduction emulation (BIT-FROZEN, feeds knn) ----
__global__ void sqnorm_warp_k(const float* __restrict__ X, float* __restrict__ sq, int C)
{
    int gw   = (blockIdx.x * blockDim.x + threadIdx.x) >> 5;
    int lane = threadIdx.x & 31;
    if (gw >= BSZ * NPTS) return;
    int b = gw / NPTS, n = gw % NPTS;
    const float* Xb = X + (size_t)b * C * NPTS + n;
    float s = 0.f;
    for (int c = lane; c < C; c += 32) {
        float v = Xb[(size_t)c * NPTS];
        s = __fadd_rn(s, __fmul_rn(v, v));
    }
    #pragma unroll
    for (int off = 16; off > 0; off >>= 1)
        s = __fadd_rn(s, __shfl_down_sync(0xffffffffu, s, off));
    if (lane == 0) sq[gw] = s;
}

// --------- W transpose (sub-slice, strided) into padded buffer ----------
__global__ void transw_k(const float* __restrict__ W, float* __restrict__ Wt,
                         int O, int C, int ldW, int coff)
{
    int i = blockIdx.x * blockDim.x + threadIdx.x;
    int ctot = (C + KT - 1) & ~(KT - 1);
    if (i >= ctot * OPAD) return;
    int c = i / OPAD, o = i % OPAD;
    Wt[i] = (c < C && o < O) ? W[(size_t)o * ldW + coff + c] : 0.f;
}

// Wt[c][o] = W[o*ldW + coff2 + c] - W[o*ldW + coff1 + c]
__global__ void transw_diff_k(const float* __restrict__ W, float* __restrict__ Wt,
                              int O, int C, int ldW, int coff1, int coff2)
{
    int i = blockIdx.x * blockDim.x + threadIdx.x;
    int ctot = (C + KT - 1) & ~(KT - 1);
    if (i >= ctot * OPAD) return;
    int c = i / OPAD, o = i % OPAD;
    Wt[i] = (c < C && o < O)
          ? W[(size_t)o * ldW + coff2 + c] - W[(size_t)o * ldW + coff1 + c] : 0.f;
}

// ---------------- cp.async helpers ----------------
__device__ __forceinline__ void cpa16(uint32_t s, const void* g, int sz)
{
    asm volatile("cp.async.cg.shared.global [%0], [%1], 16, %2;"
                 :: "r"(s), "l"(g), "r"(sz));
}
__device__ __forceinline__ void cpa_commit() { asm volatile("cp.async.commit_group;"); }
template<int N> __device__ __forceinline__ void cpa_wait()
{ asm volatile("cp.async.wait_group %0;" :: "n"(N)); }

// packed dual fp32 FMA (each half IEEE RN, same rounding as scalar FFMA)
__device__ __forceinline__ void ffma2(u64& d, u64 a, u64 b)
{
    asm("fma.rn.f32x2 %0, %1, %2, %0;" : "+l"(d) : "l"(a), "l"(b));
}
__device__ __forceinline__ u64 packdup(float a)
{
    u64 r;
    asm("mov.b64 %0, {%1, %1};" : "=l"(r) : "f"(a));
    return r;
}

// ------- double-buffered 128x128xKT SIMT sgemm, FFMA2 inner (BIT-FROZEN) -----
__global__ __launch_bounds__(256, 2) void gemm_db_k(
    const float* __restrict__ A, const float* __restrict__ X,
    const float* __restrict__ bias, float* __restrict__ Y,
    int O, int C, int M, int ldA, size_t sA, size_t sX, size_t sY)
{
    const int b = blockIdx.z;
    const float* Ab = A + (size_t)b * sA;
    const float* Xb = X + (size_t)b * sX;
    float* Yb = Y + (size_t)b * sY;
    const int m0 = blockIdx.x * 128;
    const int o0 = blockIdx.y * 128;
    const int tid = threadIdx.x;
    const int tx = tid & 15, ty = tid >> 4;

    __shared__ float As[2][KT][128];
    __shared__ float Bs[2][KT][128];

    const int rr = tid >> 4;
    const int cl = (tid & 15) * 8;

    uint32_t saA = (uint32_t)__cvta_generic_to_shared(&As[0][rr][cl]);
    uint32_t saB = (uint32_t)__cvta_generic_to_shared(&Bs[0][rr][cl]);
    const uint32_t bufoff = KT * 128 * 4;

    const int ntiles = (C + KT - 1) / KT;

    u64 acc2[2][2][4][2];
    #pragma unroll
    for (int rh = 0; rh < 2; rh++)
        #pragma unroll
        for (int ch = 0; ch < 2; ch++)
            #pragma unroll
            for (int i = 0; i < 4; i++)
                { acc2[rh][ch][i][0] = 0ull; acc2[rh][ch][i][1] = 0ull; }

    {
        int c = rr;
        int pz = (c < C) ? 16 : 0;
        int cs = (c < C) ? c : 0;
        const float* ga = Ab + (size_t)cs * ldA + o0 + cl;
        const float* gx = Xb + (size_t)cs * M + m0 + cl;
        cpa16(saA,      ga,     pz);
        cpa16(saA + 16, ga + 4, pz);
        cpa16(saB,      gx,     pz);
        cpa16(saB + 16, gx + 4, pz);
        cpa_commit();
    }

    for (int it = 0; it < ntiles; it++) {
        int buf = it & 1;
        if (it + 1 < ntiles) {
            int c = (it + 1) * KT + rr;
            int pz = (c < C) ? 16 : 0;
            int cs = (c < C) ? c : 0;
            uint32_t nb = ((it + 1) & 1) * bufoff;
            const float* ga = Ab + (size_t)cs * ldA + o0 + cl;
            const float* gx = Xb + (size_t)cs * M + m0 + cl;
            cpa16(saA + nb,      ga,     pz);
            cpa16(saA + nb + 16, ga + 4, pz);
            cpa16(saB + nb,      gx,     pz);
            cpa16(saB + nb + 16, gx + 4, pz);
            cpa_commit();
            cpa_wait<1>();
        } else {
            cpa_wait<0>();
        }
        __syncthreads();
        #pragma unroll
        for (int k = 0; k < KT; k++) {
            float a[2][4];
            *(float4*)a[0] = *(const float4*)&As[buf][k][ty * 4];
            *(float4*)a[1] = *(const float4*)&As[buf][k][64 + ty * 4];
            u64 x0[2], x1[2];
            {
                ulonglong2 v = *(const ulonglong2*)&Bs[buf][k][tx * 4];
                x0[0] = v.x; x0[1] = v.y;
            }
            {
                ulonglong2 v = *(const ulonglong2*)&Bs[buf][k][64 + tx * 4];
                x1[0] = v.x; x1[1] = v.y;
            }
            #pragma unroll
            for (int rh = 0; rh < 2; rh++)
                #pragma unroll
                for (int i = 0; i < 4; i++) {
                    u64 aa = packdup(a[rh][i]);
                    ffma2(acc2[rh][0][i][0], aa, x0[0]);
                    ffma2(acc2[rh][0][i][1], aa, x0[1]);
                    ffma2(acc2[rh][1][i][0], aa, x1[0]);
                    ffma2(acc2[rh][1][i][1], aa, x1[1]);
                }
        }
        __syncthreads();
    }

    #pragma unroll
    for (int rh = 0; rh < 2; rh++)
        #pragma unroll
        for (int i = 0; i < 4; i++) {
            int o = o0 + rh * 64 + ty * 4 + i;
            if (o < O) {
                #pragma unroll
                for (int ch = 0; ch < 2; ch++) {
                    F2U q0, q1;
                    q0.u = acc2[rh][ch][i][0];
                    q1.u = acc2[rh][ch][i][1];
                    float4 r;
                    if (bias) {
                        float bv = bias[o];
                        r.x = q0.f2.x + bv; r.y = q0.f2.y + bv;
                        r.z = q1.f2.x + bv; r.w = q1.f2.y + bv;
                    } else {
                        r.x = q0.f2.x; r.y = q0.f2.y;
                        r.z = q1.f2.x; r.w = q1.f2.y;
                    }
                    *(float4*)&Yb[(size_t)o * M + m0 + ch * 64 + tx * 4] = r;
                }
            }
        }
}

// ------- dual-source variant: rows [0,Csplit) from X, rows >= Csplit from X2 --
__global__ __launch_bounds__(256, 2) void gemm_db_dual_k(
    const float* __restrict__ A, const float* __restrict__ X,
    const float* __restrict__ X2, int Csplit,
    const float* __restrict__ bias, float* __restrict__ Y,
    int O, int C, int M, int ldA, size_t sA, size_t sX, size_t sX2, size_t sY)
{
    const int b = blockIdx.z;
    const float* Ab  = A  + (size_t)b * sA;
    const float* Xb  = X  + (size_t)b * sX;
    const float* X2b = X2 + (size_t)b * sX2;
    float* Yb = Y + (size_t)b * sY;
    const int m0 = blockIdx.x * 128;
    const int o0 = blockIdx.y * 128;
    const int tid = threadIdx.x;
    const int tx = tid & 15, ty = tid >> 4;

    __shared__ float As[2][KT][128];
    __shared__ float Bs[2][KT][128];

    const int rr = tid >> 4;
    const int cl = (tid & 15) * 8;

    uint32_t saA = (uint32_t)__cvta_generic_to_shared(&As[0][rr][cl]);
    uint32_t saB = (uint32_t)__cvta_generic_to_shared(&Bs[0][rr][cl]);
    const uint32_t bufoff = KT * 128 * 4;

    const int ntiles = (C + KT - 1) / KT;

    u64 acc2[2][2][4][2];
    #pragma unroll
    for (int rh = 0; rh < 2; rh++)
        #pragma unroll
        for (int ch = 0; ch < 2; ch++)
            #pragma unroll
            for (int i = 0; i < 4; i++)
                { acc2[rh][ch][i][0] = 0ull; acc2[rh][ch][i][1] = 0ull; }

    {
        int c = rr;
        int pz = (c < C) ? 16 : 0;
        int cs = (c < C) ? c : 0;
        const float* ga = Ab + (size_t)cs * ldA + o0 + cl;
        const float* gx = (cs < Csplit) ? Xb + (size_t)cs * M + m0 + cl
                                        : X2b + (size_t)(cs - Csplit) * M + m0 + cl;
        cpa16(saA,      ga,     pz);
        cpa16(saA + 16, ga + 4, pz);
        cpa16(saB,      gx,     pz);
        cpa16(saB + 16, gx + 4, pz);
        cpa_commit();
    }

    for (int it = 0; it < ntiles; it++) {
        int buf = it & 1;
        if (it + 1 < ntiles) {
            int c = (it + 1) * KT + rr;
            int pz = (c < C) ? 16 : 0;
            int cs = (c < C) ? c : 0;
            uint32_t nb = ((it + 1) & 1) * bufoff;
            const float* ga = Ab + (size_t)cs * ldA + o0 + cl;
            const float* gx = (cs < Csplit) ? Xb + (size_t)cs * M + m0 + cl
                                            : X2b + (size_t)(cs - Csplit) * M + m0 + cl;
            cpa16(saA + nb,      ga,     pz);
            cpa16(saA + nb + 16, ga + 4, pz);
            cpa16(saB + nb,      gx,     pz);
            cpa16(saB + nb + 16, gx + 4, pz);
            cpa_commit();
            cpa_wait<1>();
        } else {
            cpa_wait<0>();
        }
        __syncthreads();
        #pragma unroll
        for (int k = 0; k < KT; k++) {
            float a[2][4];
            *(float4*)a[0] = *(const float4*)&As[buf][k][ty * 4];
            *(float4*)a[1] = *(const float4*)&As[buf][k][64 + ty * 4];
            u64 x0[2], x1[2];
            {
                ulonglong2 v = *(const ulonglong2*)&Bs[buf][k][tx * 4];
                x0[0] = v.x; x0[1] = v.y;
            }
            {
                ulonglong2 v = *(const ulonglong2*)&Bs[buf][k][64 + tx * 4];
                x1[0] = v.x; x1[1] = v.y;
            }
            #pragma unroll
            for (int rh = 0; rh < 2; rh++)
                #pragma unroll
                for (int i = 0; i < 4; i++) {
                    u64 aa = packdup(a[rh][i]);
                    ffma2(acc2[rh][0][i][0], aa, x0[0]);
                    ffma2(acc2[rh][0][i][1], aa, x0[1]);
                    ffma2(acc2[rh][1][i][0], aa, x1[0]);
                    ffma2(acc2[rh][1][i][1], aa, x1[1]);
                }
        }
        __syncthreads();
    }

    #pragma unroll
    for (int rh = 0; rh < 2; rh++)
        #pragma unroll
        for (int i = 0; i < 4; i++) {
            int o = o0 + rh * 64 + ty * 4 + i;
            if (o < O) {
                #pragma unroll
                for (int ch = 0; ch < 2; ch++) {
                    F2U q0, q1;
                    q0.u = acc2[rh][ch][i][0];
                    q1.u = acc2[rh][ch][i][1];
                    float4 r;
                    if (bias) {
                        float bv = bias[o];
                        r.x = q0.f2.x + bv; r.y = q0.f2.y + bv;
                        r.z = q1.f2.x + bv; r.w = q1.f2.y + bv;
                    } else {
                        r.x = q0.f2.x; r.y = q0.f2.y;
                        r.z = q1.f2.x; r.w = q1.f2.y;
                    }
                    *(float4*)&Yb[(size_t)o * M + m0 + ch * 64 + tx * 4] = r;
                }
            }
        }
}

// ------- top-10: register-resident keys (round-10 best-known version) --------
__global__ void topk_k(const float* __restrict__ G, const float* __restrict__ sq,
                       int* __restrict__ idx)
{
    const int n = blockIdx.x, b = blockIdx.y;
    const float* Gr  = G + ((size_t)b * NPTS + n) * NPTS;
    const float* sqb = sq + b * NPTS;
    const int t = threadIdx.x;
    const int lane = t & 31, warp = t >> 5;
    const float sqn = sqb[n];

    float key[8];
    #pragma unroll
    for (int s = 0; s < 8; s++) {
        int j = s * 256 + t;
        key[s] = (j == n) ? FLT_MAX
               : __fadd_rn(__fadd_rn(__fmul_rn(-2.f, Gr[j]), sqb[j]), sqn);
    }

    __shared__ float swv[8];
    __shared__ int   swi[8];
    __shared__ int   win;

    for (int r = 0; r < KNN; r++) {
        float bv = key[0]; int bs = 0;
        #pragma unroll
        for (int s = 1; s < 8; s++)
            if (key[s] < bv) { bv = key[s]; bs = s; }
        int bj = bs * 256 + t;
        #pragma unroll
        for (int off = 16; off > 0; off >>= 1) {
            float ov = __shfl_down_sync(0xffffffffu, bv, off);
            int   oj = __shfl_down_sync(0xffffffffu, bj, off);
            if (ov < bv || (ov == bv && oj < bj)) { bv = ov; bj = oj; }
        }
        if (lane == 0) { swv[warp] = bv; swi[warp] = bj; }
        __syncthreads();
        if (t == 0) {
            float fv = swv[0]; int fj = swi[0];
            #pragma unroll
            for (int w = 1; w < 8; w++)
                if (swv[w] < fv || (swv[w] == fv && swi[w] < fj)) { fv = swv[w]; fj = swi[w]; }
            idx[((size_t)b * NPTS + n) * KNN + r] = fj;
            win = fj;
        }
        __syncthreads();
        int fj = win;
        if ((fj & 255) == t) key[fj >> 8] = FLT_MAX;
        __syncthreads();
    }
}

// ---------------- gather edge features (block 1 only, FROZEN path) ----------
__global__ void gather_k(const float* __restrict__ X, const int* __restrict__ idx,
                         float* __restrict__ F, int C)
{
    size_t total = (size_t)BSZ * 2 * C * MBIG;
    size_t i = (size_t)blockIdx.x * blockDim.x + threadIdx.x;
    if (i >= total) return;
    int m = (int)(i % MBIG);
    size_t r = i / MBIG;
    int c = (int)(r % (2 * C));
    int b = (int)(r / (2 * C));
    int n = m / KNN, k = m % KNN;
    if (c < C) {
        int j = idx[((size_t)b * NPTS + n) * KNN + k];
        const float* row = X + ((size_t)b * C + c) * NPTS;
        F[i] = row[j] - row[n];
    } else {
        F[i] = X[((size_t)b * C + (c - C)) * NPTS + n];
    }
}

// --- analytic BN1 stats for block2, stage 1: per-(o,b) partials -------------
__global__ void stats_ps_part_k(const float* __restrict__ P, const float* __restrict__ S,
                                const int* __restrict__ idx,
                                double* __restrict__ p1, double* __restrict__ p2, int O)
{
    const int o = blockIdx.x;
    const int b = blockIdx.y;
    const int t = threadIdx.x;
    __shared__ float prow[NPTS];
    __shared__ double r1[256], r2[256];
    const float* Pb = P + ((size_t)b * O + o) * NPTS;
    const float* Sb = S + ((size_t)b * O + o) * NPTS;
    const int*   ib = idx + (size_t)b * MBIG;
    for (int j = t; j < NPTS; j += 256) prow[j] = Pb[j];
    __syncthreads();
    double s1 = 0.0, s2 = 0.0;
    for (int n = t; n < NPTS; n += 256) {
        float sv = Sb[n];
        const int* ii = ib + n * KNN;
        float ts = 0.f, us = 0.f;
        #pragma unroll
        for (int k = 0; k < KNN; k++) {
            float p = prow[ii[k]];
            ts += p;
            us = fmaf(p, p, us);
        }
        s1 += (double)(ts + 10.f * sv);
        s2 += (double)(us + 2.f * sv * ts + 10.f * sv * sv);
    }
    r1[t] = s1; r2[t] = s2;
    __syncthreads();
    for (int w = 128; w > 0; w >>= 1) {
        if (t < w) { r1[t] += r1[t + w]; r2[t] += r2[t + w]; }
        __syncthreads();
    }
    if (t == 0) { p1[o * BSZ + b] = r1[0]; p2[o * BSZ + b] = r2[0]; }
}

// --- stage 2: deterministic finalize (ascending b) -> BN affine a/bb --------
__global__ void stats_ps_final_k(const double* __restrict__ p1, const double* __restrict__ p2,
                                 const float* __restrict__ gam, const float* __restrict__ bet,
                                 float* __restrict__ Aout, float* __restrict__ BBout, int O)
{
    int o = blockIdx.x * blockDim.x + threadIdx.x;
    if (o >= O) return;
    double s1 = 0.0, s2 = 0.0;
    #pragma unroll
    for (int b = 0; b < BSZ; b++) { s1 += p1[o * BSZ + b]; s2 += p2[o * BSZ + b]; }
    double inv = 1.0 / ((double)BSZ * (double)MBIG);
    double mu  = s1 * inv;
    double var = s2 * inv - mu * mu;
    if (var < 0.0) var = 0.0;
    float a  = rsqrtf((float)var + 1e-5f) * gam[o];
    float bb = bet[o] - (float)mu * a;
    Aout[o]  = a;
    BBout[o] = bb;
}

// -------- combine + BN affine + leaky: Y1 = leaky(a*(P[idx]+S) + bb) --------
__global__ void combine_bn_k(const float* __restrict__ P, const float* __restrict__ S,
                             const int* __restrict__ idx,
                             const float* __restrict__ A, const float* __restrict__ BB,
                             float* __restrict__ Y, int O)
{
    size_t total = (size_t)BSZ * O * MBIG;
    size_t i = (size_t)blockIdx.x * blockDim.x + threadIdx.x;
    if (i >= total) return;
    int m = (int)(i % MBIG);
    size_t r = i / MBIG;
    int o = (int)(r % O);
    int b = (int)(r / O);
    int n = m / KNN;
    int j = idx[(size_t)b * MBIG + m];
    size_t base = ((size_t)b * O + o) * NPTS;
    float v = fmaf(P[base + j] + S[base + n], A[o], BB[o]);
    Y[i] = (v >= 0.f) ? v : 0.2f * v;
}

// ------- BN statistics, two-pass (BIT-FROZEN: block-1 stats feed knn-2) ------
__global__ void bn_stats_k(const float* __restrict__ Y, float* __restrict__ mean,
                           float* __restrict__ var, int O, int M)
{
    const int c = blockIdx.x;
    const int t = threadIdx.x;
    __shared__ float ss[256];
    __shared__ float mu_s;
    float s = 0.f;
    for (int b = 0; b < BSZ; b++) {
        const float* p = Y + ((size_t)b * O + c) * M;
        for (int m = t; m < M; m += 256) s += p[m];
    }
    ss[t] = s;
    __syncthreads();
    for (int w = 128; w > 0; w >>= 1) {
        if (t < w) ss[t] += ss[t + w];
        __syncthreads();
    }
    if (t == 0) {
        float mu = ss[0] / ((float)BSZ * (float)M);
        mean[c] = mu;
        mu_s = mu;
    }
    __syncthreads();
    const float mu = mu_s;
    float s2 = 0.f;
    for (int b = 0; b < BSZ; b++) {
        const float* p = Y + ((size_t)b * O + c) * M;
        for (int m = t; m < M; m += 256) { float d = p[m] - mu; s2 += d * d; }
    }
    ss[t] = s2;
    __syncthreads();
    for (int w = 128; w > 0; w >>= 1) {
        if (t < w) ss[t] += ss[t + w];
        __syncthreads();
    }
    if (t == 0) var[c] = ss[0] / ((float)BSZ * (float)M);
}

// ------- BN statistics, single-pass (tolerance paths) ----------
__global__ void bn_stats_fast_k(const float* __restrict__ Y, float* __restrict__ mean,
                                float* __restrict__ var, int O, int M)
{
    const int c = blockIdx.x;
    const int t = threadIdx.x;
    __shared__ float ss[256], ss2[256];
    float s = 0.f, s2 = 0.f;
    for (int b = 0; b < BSZ; b++) {
        const float* p = Y + ((size_t)b * O + c) * M;
        for (int m = t * 4; m < M; m += 1024) {
            float4 v = *(const float4*)(p + m);
            s += v.x; s2 = fmaf(v.x, v.x, s2);
            s += v.y; s2 = fmaf(v.y, v.y, s2);
            s += v.z; s2 = fmaf(v.z, v.z, s2);
            s += v.w; s2 = fmaf(v.w, v.w, s2);
        }
    }
    ss[t] = s; ss2[t] = s2;
    __syncthreads();
    for (int w = 128; w > 0; w >>= 1) {
        if (t < w) { ss[t] += ss[t + w]; ss2[t] += ss2[t + w]; }
        __syncthreads();
    }
    if (t == 0) {
        float inv = 1.f / ((float)BSZ * (float)M);
        float mu  = ss[0] * inv;
        mean[c] = mu;
        var[c]  = fmaxf(ss2[0] * inv - mu * mu, 0.f);
    }
}

// -------- apply BN affine + leaky relu, in place ----
__global__ void bn_leaky_k(float* __restrict__ Y, const float* __restrict__ mean,
                           const float* __restrict__ var, const float* __restrict__ gam,
                           const float* __restrict__ bet, int O, size_t M)
{
    size_t total = (size_t)BSZ * O * M;
    size_t i = ((size_t)blockIdx.x * blockDim.x + threadIdx.x) * 4;
    if (i >= total) return;
    int c = (int)((i / M) % O);
    float a  = rsqrtf(var[c] + 1e-5f) * gam[c];
    float bb = bet[c] - mean[c] * a;
    float4 v = *(float4*)(Y + i);
    float tt;
    tt = fmaf(v.x, a, bb); v.x = (tt >= 0.f) ? tt : 0.2f * tt;
    tt = fmaf(v.y, a, bb); v.y = (tt >= 0.f) ? tt : 0.2f * tt;
    tt = fmaf(v.z, a, bb); v.z = (tt >= 0.f) ? tt : 0.2f * tt;
    tt = fmaf(v.w, a, bb); v.w = (tt >= 0.f) ? tt : 0.2f * tt;
    *(float4*)(Y + i) = v;
}

// ---- BN + leaky + max over K, exact ref op order (BIT-FROZEN) ----
__global__ void bn_leaky_maxk_k(const float* __restrict__ Y, const float* __restrict__ mean,
                                const float* __restrict__ var, const float* __restrict__ gam,
                                const float* __restrict__ bet, float* __restrict__ out, int O)
{
    size_t total = (size_t)BSZ * O * NPTS;
    size_t i = (size_t)blockIdx.x * blockDim.x + threadIdx.x;
    if (i >= total) return;
    int n = (int)(i % NPTS);
    int c = (int)((i / NPTS) % O);
    int b = (int)(i / ((size_t)NPTS * O));
    const float mu = mean[c];
    const float s  = __fsqrt_rn(__fadd_rn(var[c], 1e-5f));
    const float g  = gam[c];
    const float be = bet[c];
    const float* p = Y + ((size_t)b * O + c) * MBIG + (size_t)n * KNN;
    float sel = p[0];
    if (g >= 0.f) {
        #pragma unroll
        for (int k = 1; k < KNN; k++) sel = fmaxf(sel, p[k]);
    } else {
        #pragma unroll
        for (int k = 1; k < KNN; k++) sel = fminf(sel, p[k]);
    }
    float t = __fdiv_rn(__fsub_rn(sel, mu), s);
    t = __fadd_rn(__fmul_rn(t, g), be);
    t = (t >= 0.f) ? t : __fmul_rn(0.2f, t);
    out[i] = t;
}

// ============================ host launcher ============================
static inline void* symaddr(const void* sym)
{
    void* p = nullptr;
    cudaGetSymbolAddress(&p, sym);
    return p;
}

extern "C" void kernel_launch(void* const* d_in, const int* in_sizes, int n_in,
                              void* d_out, int out_size)
{
    (void)in_sizes; (void)n_in; (void)out_size;
    const float* x = (const float*)d_in[0];

    const float* P24[24];
    for (int i = 0; i < 24; i++) P24[i] = (const float*)d_in[1 + i];
    #define W1(p)  P24[(p)*8 + 0]
    #define B1(p)  P24[(p)*8 + 1]
    #define G1(p)  P24[(p)*8 + 2]
    #define BE1(p) P24[(p)*8 + 3]
    #define W2(p)  P24[(p)*8 + 4]
    #define B2(p)  P24[(p)*8 + 5]
    #define G2(p)  P24[(p)*8 + 6]
    #define BE2(p) P24[(p)*8 + 7]

    float* G    = (float*)symaddr(g_G);
    float* SQ   = (float*)symaddr(g_sq);
    int*   IDX  = (int*)  symaddr(g_idx);
    float* FEAT = (float*)symaddr(g_feat);
    float* Y1   = (float*)symaddr(g_y1);
    float* Y2   = (float*)symaddr(g_y2);
    float* X1   = (float*)symaddr(g_x1);
    float* X2   = (float*)symaddr(g_x2);
    float* Y3   = (float*)symaddr(g_y3);
    float* PP   = (float*)symaddr(g_P);
    float* SS   = (float*)symaddr(g_S);
    float* WT   = (float*)symaddr(g_wt);
    double* P1  = (double*)symaddr(g_p1);
    double* P2  = (double*)symaddr(g_p2);
    float* MEAN = (float*)symaddr(g_mean);
    float* VAR  = (float*)symaddr(g_var);
    float* OUT  = (float*)d_out;

    const int ew = 256;
    #define GS(total) (unsigned)(((total) + ew - 1) / ew)
    #define CT(C) (((C) + KT - 1) & ~(KT - 1))

    auto conv = [&](const float* W, const float* bias, const float* Xin, float* Yout,
                    int O, int C, int M) {
        transw_k<<<GS(CT(C) * OPAD), ew>>>(W, WT, O, C, C, 0);
        gemm_db_k<<<dim3(M / 128, (O + 127) / 128, BSZ), 256>>>(
            WT, Xin, bias, Yout, O, C, M, OPAD, 0, (size_t)C * M, (size_t)O * M);
    };

    auto knn = [&](const float* xin, int C) {
        sqnorm_warp_k<<<(BSZ * NPTS * 32 + 255) / 256, 256>>>(xin, SQ, C);
        gemm_db_k<<<dim3(NPTS / 128, NPTS / 128, BSZ), 256>>>(
            xin, xin, nullptr, G, NPTS, C, NPTS,
            NPTS, (size_t)C * NPTS, (size_t)C * NPTS, (size_t)NPTS * NPTS);
        topk_k<<<dim3(NPTS, BSZ), 256>>>(G, SQ, IDX);
    };

    // ================= block 1 (FROZEN path: produces x1 -> knn-2) ============
    {
        const int C = 64, O1 = 152, O2 = 181;
        knn(x, C);
        gather_k<<<GS((size_t)BSZ * 2 * C * MBIG), ew>>>(x, IDX, FEAT, C);
        conv(W1(0), B1(0), FEAT, Y1, O1, 2 * C, MBIG);
        bn_stats_k<<<O1, 256>>>(Y1, MEAN, VAR, O1, MBIG);
        bn_leaky_k<<<GS((size_t)BSZ * O1 * MBIG / 4), ew>>>(Y1, MEAN, VAR, G1(0), BE1(0), O1, MBIG);
        conv(W2(0), B2(0), Y1, Y2, O2, O1, MBIG);
        bn_stats_k<<<O2, 256>>>(Y2, MEAN, VAR, O2, MBIG);
        bn_leaky_maxk_k<<<GS((size_t)BSZ * O2 * NPTS), ew>>>(Y2, MEAN, VAR, G2(0), BE2(0), X1, O2);
    }

    // ====== block 2 (tolerance path: split conv1 + parallel analytic stats) ==
    {
        const int C = 181, O1 = 430, O2 = 512;
        knn(X1, C);
        transw_k<<<GS(CT(C) * OPAD), ew>>>(W1(1), WT, O1, C, 2 * C, 0);
        gemm_db_k<<<dim3(NPTS / 128, (O1 + 127) / 128, BSZ), 256>>>(
            WT, X1, nullptr, PP, O1, C, NPTS, OPAD, 0, (size_t)C * NPTS, (size_t)O1 * NPTS);
        transw_diff_k<<<GS(CT(C) * OPAD), ew>>>(W1(1), WT, O1, C, 2 * C, 0, C);
        gemm_db_k<<<dim3(NPTS / 128, (O1 + 127) / 128, BSZ), 256>>>(
            WT, X1, B1(1), SS, O1, C, NPTS, OPAD, 0, (size_t)C * NPTS, (size_t)O1 * NPTS);
        stats_ps_part_k<<<dim3(O1, BSZ), 256>>>(PP, SS, IDX, P1, P2, O1);
        stats_ps_final_k<<<(O1 + 255) / 256, 256>>>(P1, P2, G1(1), BE1(1), MEAN, VAR, O1);
        combine_bn_k<<<GS((size_t)BSZ * O1 * MBIG), ew>>>(PP, SS, IDX, MEAN, VAR, Y1, O1);
        conv(W2(1), B2(1), Y1, Y2, O2, O1, MBIG);
        bn_stats_fast_k<<<O2, 256>>>(Y2, MEAN, VAR, O2, MBIG);
        bn_leaky_maxk_k<<<GS((size_t)BSZ * O2 * NPTS), ew>>>(Y2, MEAN, VAR, G2(1), BE2(1), X2, O2);
    }

    // ====== block 3 (tolerance path; concat fused into dual-source GEMM) =====
    {
        const int C = 693, Csplit = 181, O1 = 595, O2 = 512;
        transw_k<<<GS(CT(C) * OPAD), ew>>>(W1(2), WT, O1, C, C, 0);
        gemm_db_dual_k<<<dim3(NPTS / 128, (O1 + 127) / 128, BSZ), 256>>>(
            WT, X1, X2, Csplit, B1(2), Y3, O1, C, NPTS, OPAD,
            0, (size_t)Csplit * NPTS, (size_t)512 * NPTS, (size_t)O1 * NPTS);
        bn_stats_fast_k<<<O1, 256>>>(Y3, MEAN, VAR, O1, NPTS);
        bn_leaky_k<<<GS((size_t)BSZ * O1 * NPTS / 4), ew>>>(Y3, MEAN, VAR, G1(2), BE1(2), O1, NPTS);
        conv(W2(2), B2(2), Y3, OUT, O2, O1, NPTS);
        bn_stats_fast_k<<<O2, 256>>>(OUT, MEAN, VAR, O2, NPTS);
        bn_leaky_k<<<GS((size_t)BSZ * O2 * NPTS / 4), ew>>>(OUT, MEAN, VAR, G2(2), BE2(2), O2, NPTS);
    }
}

// round 17
// speedup vs baseline: 1.0549x; 1.0149x over previous
#include <cuda_runtime.h>
#include <cfloat>
#include <cstdint>

#define BSZ   8
#define NPTS  2048
#define KNN   10
#define MBIG  (NPTS * KNN)   // 20480
#define OPAD  768            // padded O stride for transposed weights
#define CPAD  704            // padded C rows (704 = 44*16, covers 693)
#define KT    16             // GEMM k-tile depth

typedef unsigned long long u64;
union F2U { float2 f2; u64 u; };

// ---------------- scratch (device globals; allocation-free) ----------------
__device__ float g_G   [(size_t)BSZ * NPTS * NPTS];     // gram
__device__ float g_sq  [BSZ * NPTS];
__device__ int   g_idx [BSZ * NPTS * KNN];
__device__ float g_feat[(size_t)BSZ * 362 * MBIG];      // edge features (block 1)
__device__ float g_y1  [(size_t)BSZ * 430 * MBIG];      // conv1 out (max O=430)
__device__ float g_y2  [(size_t)BSZ * 512 * MBIG];      // conv2 out (max O=512)
__device__ float g_x1  [BSZ * 181 * NPTS];
__device__ float g_x2  [BSZ * 512 * NPTS];
__device__ float g_y3  [BSZ * 595 * NPTS];
__device__ float g_P   [BSZ * 430 * NPTS];              // split-conv P
__device__ float g_S   [BSZ * 430 * NPTS];              // split-conv S (incl bias)
__device__ float g_wt  [CPAD * OPAD];                   // transposed + padded weights
__device__ double g_p1 [512 * BSZ];                     // stats partials (sum)
__device__ double g_p2 [512 * BSZ];                     // stats partials (sumsq)
__device__ float g_mean[1024];
__device__ float g_var [1024];

// ---- squared norms: XLA row-reduction emulation (BIT-FROZEN, feeds knn) ----
__global__ void sqnorm_warp_k(const float* __restrict__ X, float* __restrict__ sq, int C)
{
    int gw   = (blockIdx.x * blockDim.x + threadIdx.x) >> 5;
    int lane = threadIdx.x & 31;
    if (gw >= BSZ * NPTS) return;
    int b = gw / NPTS, n = gw % NPTS;
    const float* Xb = X + (size_t)b * C * NPTS + n;
    float s = 0.f;
    for (int c = lane; c < C; c += 32) {
        float v = Xb[(size_t)c * NPTS];
        s = __fadd_rn(s, __fmul_rn(v, v));
    }
    #pragma unroll
    for (int off = 16; off > 0; off >>= 1)
        s = __fadd_rn(s, __shfl_down_sync(0xffffffffu, s, off));
    if (lane == 0) sq[gw] = s;
}

// --------- W transpose (sub-slice, strided) into padded buffer ----------
__global__ void transw_k(const float* __restrict__ W, float* __restrict__ Wt,
                         int O, int C, int ldW, int coff)
{
    int i = blockIdx.x * blockDim.x + threadIdx.x;
    int ctot = (C + KT - 1) & ~(KT - 1);
    if (i >= ctot * OPAD) return;
    int c = i / OPAD, o = i % OPAD;
    Wt[i] = (c < C && o < O) ? W[(size_t)o * ldW + coff + c] : 0.f;
}

// Wt[c][o] = W[o*ldW + coff2 + c] - W[o*ldW + coff1 + c]
__global__ void transw_diff_k(const float* __restrict__ W, float* __restrict__ Wt,
                              int O, int C, int ldW, int coff1, int coff2)
{
    int i = blockIdx.x * blockDim.x + threadIdx.x;
    int ctot = (C + KT - 1) & ~(KT - 1);
    if (i >= ctot * OPAD) return;
    int c = i / OPAD, o = i % OPAD;
    Wt[i] = (c < C && o < O)
          ? W[(size_t)o * ldW + coff2 + c] - W[(size_t)o * ldW + coff1 + c] : 0.f;
}

// ---------------- cp.async helpers ----------------
__device__ __forceinline__ void cpa16(uint32_t s, const void* g, int sz)
{
    asm volatile("cp.async.cg.shared.global [%0], [%1], 16, %2;"
                 :: "r"(s), "l"(g), "r"(sz));
}
__device__ __forceinline__ void cpa_commit() { asm volatile("cp.async.commit_group;"); }
template<int N> __device__ __forceinline__ void cpa_wait()
{ asm volatile("cp.async.wait_group %0;" :: "n"(N)); }

// packed dual fp32 FMA (each half IEEE RN, same rounding as scalar FFMA)
__device__ __forceinline__ void ffma2(u64& d, u64 a, u64 b)
{
    asm("fma.rn.f32x2 %0, %1, %2, %0;" : "+l"(d) : "l"(a), "l"(b));
}
__device__ __forceinline__ u64 packdup(float a)
{
    u64 r;
    asm("mov.b64 %0, {%1, %1};" : "=l"(r) : "f"(a));
    return r;
}

// ------- double-buffered 128x128xKT SIMT sgemm, FFMA2 inner (BIT-FROZEN) -----
__global__ __launch_bounds__(256, 2) void gemm_db_k(
    const float* __restrict__ A, const float* __restrict__ X,
    const float* __restrict__ bias, float* __restrict__ Y,
    int O, int C, int M, int ldA, size_t sA, size_t sX, size_t sY)
{
    const int b = blockIdx.z;
    const float* Ab = A + (size_t)b * sA;
    const float* Xb = X + (size_t)b * sX;
    float* Yb = Y + (size_t)b * sY;
    const int m0 = blockIdx.x * 128;
    const int o0 = blockIdx.y * 128;
    const int tid = threadIdx.x;
    const int tx = tid & 15, ty = tid >> 4;

    __shared__ float As[2][KT][128];
    __shared__ float Bs[2][KT][128];

    const int rr = tid >> 4;
    const int cl = (tid & 15) * 8;

    uint32_t saA = (uint32_t)__cvta_generic_to_shared(&As[0][rr][cl]);
    uint32_t saB = (uint32_t)__cvta_generic_to_shared(&Bs[0][rr][cl]);
    const uint32_t bufoff = KT * 128 * 4;

    const int ntiles = (C + KT - 1) / KT;

    u64 acc2[2][2][4][2];
    #pragma unroll
    for (int rh = 0; rh < 2; rh++)
        #pragma unroll
        for (int ch = 0; ch < 2; ch++)
            #pragma unroll
            for (int i = 0; i < 4; i++)
                { acc2[rh][ch][i][0] = 0ull; acc2[rh][ch][i][1] = 0ull; }

    {
        int c = rr;
        int pz = (c < C) ? 16 : 0;
        int cs = (c < C) ? c : 0;
        const float* ga = Ab + (size_t)cs * ldA + o0 + cl;
        const float* gx = Xb + (size_t)cs * M + m0 + cl;
        cpa16(saA,      ga,     pz);
        cpa16(saA + 16, ga + 4, pz);
        cpa16(saB,      gx,     pz);
        cpa16(saB + 16, gx + 4, pz);
        cpa_commit();
    }

    for (int it = 0; it < ntiles; it++) {
        int buf = it & 1;
        if (it + 1 < ntiles) {
            int c = (it + 1) * KT + rr;
            int pz = (c < C) ? 16 : 0;
            int cs = (c < C) ? c : 0;
            uint32_t nb = ((it + 1) & 1) * bufoff;
            const float* ga = Ab + (size_t)cs * ldA + o0 + cl;
            const float* gx = Xb + (size_t)cs * M + m0 + cl;
            cpa16(saA + nb,      ga,     pz);
            cpa16(saA + nb + 16, ga + 4, pz);
            cpa16(saB + nb,      gx,     pz);
            cpa16(saB + nb + 16, gx + 4, pz);
            cpa_commit();
            cpa_wait<1>();
        } else {
            cpa_wait<0>();
        }
        __syncthreads();
        #pragma unroll
        for (int k = 0; k < KT; k++) {
            float a[2][4];
            *(float4*)a[0] = *(const float4*)&As[buf][k][ty * 4];
            *(float4*)a[1] = *(const float4*)&As[buf][k][64 + ty * 4];
            u64 x0[2], x1[2];
            {
                ulonglong2 v = *(const ulonglong2*)&Bs[buf][k][tx * 4];
                x0[0] = v.x; x0[1] = v.y;
            }
            {
                ulonglong2 v = *(const ulonglong2*)&Bs[buf][k][64 + tx * 4];
                x1[0] = v.x; x1[1] = v.y;
            }
            #pragma unroll
            for (int rh = 0; rh < 2; rh++)
                #pragma unroll
                for (int i = 0; i < 4; i++) {
                    u64 aa = packdup(a[rh][i]);
                    ffma2(acc2[rh][0][i][0], aa, x0[0]);
                    ffma2(acc2[rh][0][i][1], aa, x0[1]);
                    ffma2(acc2[rh][1][i][0], aa, x1[0]);
                    ffma2(acc2[rh][1][i][1], aa, x1[1]);
                }
        }
        __syncthreads();
    }

    #pragma unroll
    for (int rh = 0; rh < 2; rh++)
        #pragma unroll
        for (int i = 0; i < 4; i++) {
            int o = o0 + rh * 64 + ty * 4 + i;
            if (o < O) {
                #pragma unroll
                for (int ch = 0; ch < 2; ch++) {
                    F2U q0, q1;
                    q0.u = acc2[rh][ch][i][0];
                    q1.u = acc2[rh][ch][i][1];
                    float4 r;
                    if (bias) {
                        float bv = bias[o];
                        r.x = q0.f2.x + bv; r.y = q0.f2.y + bv;
                        r.z = q1.f2.x + bv; r.w = q1.f2.y + bv;
                    } else {
                        r.x = q0.f2.x; r.y = q0.f2.y;
                        r.z = q1.f2.x; r.w = q1.f2.y;
                    }
                    *(float4*)&Yb[(size_t)o * M + m0 + ch * 64 + tx * 4] = r;
                }
            }
        }
}

// ------- triangular gram clone: identical body, skips blocks with m0 < n0 ----
// (per-block code identical to gemm_db_k -> upper-triangle bits unchanged)
__global__ __launch_bounds__(256, 2) void gemm_tri_k(
    const float* __restrict__ A, const float* __restrict__ X,
    float* __restrict__ Y, int C, size_t sX, size_t sY)
{
    if (blockIdx.x < blockIdx.y) return;   // compute only m-block >= n-block
    const int b = blockIdx.z;
    const float* Ab = A + (size_t)b * sX;
    const float* Xb = X + (size_t)b * sX;
    float* Yb = Y + (size_t)b * sY;
    const int m0 = blockIdx.x * 128;
    const int o0 = blockIdx.y * 128;
    const int tid = threadIdx.x;
    const int tx = tid & 15, ty = tid >> 4;
    const int M = NPTS, ldA = NPTS;

    __shared__ float As[2][KT][128];
    __shared__ float Bs[2][KT][128];

    const int rr = tid >> 4;
    const int cl = (tid & 15) * 8;

    uint32_t saA = (uint32_t)__cvta_generic_to_shared(&As[0][rr][cl]);
    uint32_t saB = (uint32_t)__cvta_generic_to_shared(&Bs[0][rr][cl]);
    const uint32_t bufoff = KT * 128 * 4;

    const int ntiles = (C + KT - 1) / KT;

    u64 acc2[2][2][4][2];
    #pragma unroll
    for (int rh = 0; rh < 2; rh++)
        #pragma unroll
        for (int ch = 0; ch < 2; ch++)
            #pragma unroll
            for (int i = 0; i < 4; i++)
                { acc2[rh][ch][i][0] = 0ull; acc2[rh][ch][i][1] = 0ull; }

    {
        int c = rr;
        int pz = (c < C) ? 16 : 0;
        int cs = (c < C) ? c : 0;
        const float* ga = Ab + (size_t)cs * ldA + o0 + cl;
        const float* gx = Xb + (size_t)cs * M + m0 + cl;
        cpa16(saA,      ga,     pz);
        cpa16(saA + 16, ga + 4, pz);
        cpa16(saB,      gx,     pz);
        cpa16(saB + 16, gx + 4, pz);
        cpa_commit();
    }

    for (int it = 0; it < ntiles; it++) {
        int buf = it & 1;
        if (it + 1 < ntiles) {
            int c = (it + 1) * KT + rr;
            int pz = (c < C) ? 16 : 0;
            int cs = (c < C) ? c : 0;
            uint32_t nb = ((it + 1) & 1) * bufoff;
            const float* ga = Ab + (size_t)cs * ldA + o0 + cl;
            const float* gx = Xb + (size_t)cs * M + m0 + cl;
            cpa16(saA + nb,      ga,     pz);
            cpa16(saA + nb + 16, ga + 4, pz);
            cpa16(saB + nb,      gx,     pz);
            cpa16(saB + nb + 16, gx + 4, pz);
            cpa_commit();
            cpa_wait<1>();
        } else {
            cpa_wait<0>();
        }
        __syncthreads();
        #pragma unroll
        for (int k = 0; k < KT; k++) {
            float a[2][4];
            *(float4*)a[0] = *(const float4*)&As[buf][k][ty * 4];
            *(float4*)a[1] = *(const float4*)&As[buf][k][64 + ty * 4];
            u64 x0[2], x1[2];
            {
                ulonglong2 v = *(const ulonglong2*)&Bs[buf][k][tx * 4];
                x0[0] = v.x; x0[1] = v.y;
            }
            {
                ulonglong2 v = *(const ulonglong2*)&Bs[buf][k][64 + tx * 4];
                x1[0] = v.x; x1[1] = v.y;
            }
            #pragma unroll
            for (int rh = 0; rh < 2; rh++)
                #pragma unroll
                for (int i = 0; i < 4; i++) {
                    u64 aa = packdup(a[rh][i]);
                    ffma2(acc2[rh][0][i][0], aa, x0[0]);
                    ffma2(acc2[rh][0][i][1], aa, x0[1]);
                    ffma2(acc2[rh][1][i][0], aa, x1[0]);
                    ffma2(acc2[rh][1][i][1], aa, x1[1]);
                }
        }
        __syncthreads();
    }

    #pragma unroll
    for (int rh = 0; rh < 2; rh++)
        #pragma unroll
        for (int i = 0; i < 4; i++) {
            int o = o0 + rh * 64 + ty * 4 + i;
            #pragma unroll
            for (int ch = 0; ch < 2; ch++) {
                F2U q0, q1;
                q0.u = acc2[rh][ch][i][0];
                q1.u = acc2[rh][ch][i][1];
                float4 r = make_float4(q0.f2.x, q0.f2.y, q1.f2.x, q1.f2.y);
                *(float4*)&Yb[(size_t)o * M + m0 + ch * 64 + tx * 4] = r;
            }
        }
}

// ---- mirror strictly-lower 128-blocks from upper triangle (bit-exact) ------
__global__ __launch_bounds__(256) void mirror_k(float* __restrict__ G)
{
    const int bm = blockIdx.x;   // dest column block
    const int bn = blockIdx.y;   // dest row block
    if (bm >= bn) return;        // only strictly-lower dest blocks
    float* Gb = G + (size_t)blockIdx.z * NPTS * NPTS;
    __shared__ float tile[32][33];
    const int tx = threadIdx.x & 31, ty = threadIdx.x >> 5;   // 32 x 8
    #pragma unroll
    for (int sn = 0; sn < 128; sn += 32) {
        #pragma unroll
        for (int sm = 0; sm < 128; sm += 32) {
            // src: rows (bm*128+sm+r), cols (bn*128+sn+tx)  [upper triangle]
            #pragma unroll
            for (int r = ty; r < 32; r += 8)
                tile[r][tx] = Gb[(size_t)(bm * 128 + sm + r) * NPTS + bn * 128 + sn + tx];
            __syncthreads();
            // dest: rows (bn*128+sn+r), cols (bm*128+sm+tx)
            #pragma unroll
            for (int r = ty; r < 32; r += 8)
                Gb[(size_t)(bn * 128 + sn + r) * NPTS + bm * 128 + sm + tx] = tile[tx][r];
            __syncthreads();
        }
    }
}

// ------- dual-source variant: rows [0,Csplit) from X, rows >= Csplit from X2 --
__global__ __launch_bounds__(256, 2) void gemm_db_dual_k(
    const float* __restrict__ A, const float* __restrict__ X,
    const float* __restrict__ X2, int Csplit,
    const float* __restrict__ bias, float* __restrict__ Y,
    int O, int C, int M, int ldA, size_t sA, size_t sX, size_t sX2, size_t sY)
{
    const int b = blockIdx.z;
    const float* Ab  = A  + (size_t)b * sA;
    const float* Xb  = X  + (size_t)b * sX;
    const float* X2b = X2 + (size_t)b * sX2;
    float* Yb = Y + (size_t)b * sY;
    const int m0 = blockIdx.x * 128;
    const int o0 = blockIdx.y * 128;
    const int tid = threadIdx.x;
    const int tx = tid & 15, ty = tid >> 4;

    __shared__ float As[2][KT][128];
    __shared__ float Bs[2][KT][128];

    const int rr = tid >> 4;
    const int cl = (tid & 15) * 8;

    uint32_t saA = (uint32_t)__cvta_generic_to_shared(&As[0][rr][cl]);
    uint32_t saB = (uint32_t)__cvta_generic_to_shared(&Bs[0][rr][cl]);
    const uint32_t bufoff = KT * 128 * 4;

    const int ntiles = (C + KT - 1) / KT;

    u64 acc2[2][2][4][2];
    #pragma unroll
    for (int rh = 0; rh < 2; rh++)
        #pragma unroll
        for (int ch = 0; ch < 2; ch++)
            #pragma unroll
            for (int i = 0; i < 4; i++)
                { acc2[rh][ch][i][0] = 0ull; acc2[rh][ch][i][1] = 0ull; }

    {
        int c = rr;
        int pz = (c < C) ? 16 : 0;
        int cs = (c < C) ? c : 0;
        const float* ga = Ab + (size_t)cs * ldA + o0 + cl;
        const float* gx = (cs < Csplit) ? Xb + (size_t)cs * M + m0 + cl
                                        : X2b + (size_t)(cs - Csplit) * M + m0 + cl;
        cpa16(saA,      ga,     pz);
        cpa16(saA + 16, ga + 4, pz);
        cpa16(saB,      gx,     pz);
        cpa16(saB + 16, gx + 4, pz);
        cpa_commit();
    }

    for (int it = 0; it < ntiles; it++) {
        int buf = it & 1;
        if (it + 1 < ntiles) {
            int c = (it + 1) * KT + rr;
            int pz = (c < C) ? 16 : 0;
            int cs = (c < C) ? c : 0;
            uint32_t nb = ((it + 1) & 1) * bufoff;
            const float* ga = Ab + (size_t)cs * ldA + o0 + cl;
            const float* gx = (cs < Csplit) ? Xb + (size_t)cs * M + m0 + cl
                                            : X2b + (size_t)(cs - Csplit) * M + m0 + cl;
            cpa16(saA + nb,      ga,     pz);
            cpa16(saA + nb + 16, ga + 4, pz);
            cpa16(saB + nb,      gx,     pz);
            cpa16(saB + nb + 16, gx + 4, pz);
            cpa_commit();
            cpa_wait<1>();
        } else {
            cpa_wait<0>();
        }
        __syncthreads();
        #pragma unroll
        for (int k = 0; k < KT; k++) {
            float a[2][4];
            *(float4*)a[0] = *(const float4*)&As[buf][k][ty * 4];
            *(float4*)a[1] = *(const float4*)&As[buf][k][64 + ty * 4];
            u64 x0[2], x1[2];
            {
                ulonglong2 v = *(const ulonglong2*)&Bs[buf][k][tx * 4];
                x0[0] = v.x; x0[1] = v.y;
            }
            {
                ulonglong2 v = *(const ulonglong2*)&Bs[buf][k][64 + tx * 4];
                x1[0] = v.x; x1[1] = v.y;
            }
            #pragma unroll
            for (int rh = 0; rh < 2; rh++)
                #pragma unroll
                for (int i = 0; i < 4; i++) {
                    u64 aa = packdup(a[rh][i]);
                    ffma2(acc2[rh][0][i][0], aa, x0[0]);
                    ffma2(acc2[rh][0][i][1], aa, x0[1]);
                    ffma2(acc2[rh][1][i][0], aa, x1[0]);
                    ffma2(acc2[rh][1][i][1], aa, x1[1]);
                }
        }
        __syncthreads();
    }

    #pragma unroll
    for (int rh = 0; rh < 2; rh++)
        #pragma unroll
        for (int i = 0; i < 4; i++) {
            int o = o0 + rh * 64 + ty * 4 + i;
            if (o < O) {
                #pragma unroll
                for (int ch = 0; ch < 2; ch++) {
                    F2U q0, q1;
                    q0.u = acc2[rh][ch][i][0];
                    q1.u = acc2[rh][ch][i][1];
                    float4 r;
                    if (bias) {
                        float bv = bias[o];
                        r.x = q0.f2.x + bv; r.y = q0.f2.y + bv;
                        r.z = q1.f2.x + bv; r.w = q1.f2.y + bv;
                    } else {
                        r.x = q0.f2.x; r.y = q0.f2.y;
                        r.z = q1.f2.x; r.w = q1.f2.y;
                    }
                    *(float4*)&Yb[(size_t)o * M + m0 + ch * 64 + tx * 4] = r;
                }
            }
        }
}

// ------- top-10: register-resident keys (round-10 best-known version) --------
__global__ void topk_k(const float* __restrict__ G, const float* __restrict__ sq,
                       int* __restrict__ idx)
{
    const int n = blockIdx.x, b = blockIdx.y;
    const float* Gr  = G + ((size_t)b * NPTS + n) * NPTS;
    const float* sqb = sq + b * NPTS;
    const int t = threadIdx.x;
    const int lane = t & 31, warp = t >> 5;
    const float sqn = sqb[n];

    float key[8];
    #pragma unroll
    for (int s = 0; s < 8; s++) {
        int j = s * 256 + t;
        key[s] = (j == n) ? FLT_MAX
               : __fadd_rn(__fadd_rn(__fmul_rn(-2.f, Gr[j]), sqb[j]), sqn);
    }

    __shared__ float swv[8];
    __shared__ int   swi[8];
    __shared__ int   win;

    for (int r = 0; r < KNN; r++) {
        float bv = key[0]; int bs = 0;
        #pragma unroll
        for (int s = 1; s < 8; s++)
            if (key[s] < bv) { bv = key[s]; bs = s; }
        int bj = bs * 256 + t;
        #pragma unroll
        for (int off = 16; off > 0; off >>= 1) {
            float ov = __shfl_down_sync(0xffffffffu, bv, off);
            int   oj = __shfl_down_sync(0xffffffffu, bj, off);
            if (ov < bv || (ov == bv && oj < bj)) { bv = ov; bj = oj; }
        }
        if (lane == 0) { swv[warp] = bv; swi[warp] = bj; }
        __syncthreads();
        if (t == 0) {
            float fv = swv[0]; int fj = swi[0];
            #pragma unroll
            for (int w = 1; w < 8; w++)
                if (swv[w] < fv || (swv[w] == fv && swi[w] < fj)) { fv = swv[w]; fj = swi[w]; }
            idx[((size_t)b * NPTS + n) * KNN + r] = fj;
            win = fj;
        }
        __syncthreads();
        int fj = win;
        if ((fj & 255) == t) key[fj >> 8] = FLT_MAX;
        __syncthreads();
    }
}

// ---------------- gather edge features (block 1 only, FROZEN path) ----------
__global__ void gather_k(const float* __restrict__ X, const int* __restrict__ idx,
                         float* __restrict__ F, int C)
{
    size_t total = (size_t)BSZ * 2 * C * MBIG;
    size_t i = (size_t)blockIdx.x * blockDim.x + threadIdx.x;
    if (i >= total) return;
    int m = (int)(i % MBIG);
    size_t r = i / MBIG;
    int c = (int)(r % (2 * C));
    int b = (int)(r / (2 * C));
    int n = m / KNN, k = m % KNN;
    if (c < C) {
        int j = idx[((size_t)b * NPTS + n) * KNN + k];
        const float* row = X + ((size_t)b * C + c) * NPTS;
        F[i] = row[j] - row[n];
    } else {
        F[i] = X[((size_t)b * C + (c - C)) * NPTS + n];
    }
}

// --- analytic BN1 stats for block2, stage 1: per-(o,b) partials -------------
__global__ void stats_ps_part_k(const float* __restrict__ P, const float* __restrict__ S,
                                const int* __restrict__ idx,
                                double* __restrict__ p1, double* __restrict__ p2, int O)
{
    const int o = blockIdx.x;
    const int b = blockIdx.y;
    const int t = threadIdx.x;
    __shared__ float prow[NPTS];
    __shared__ double r1[256], r2[256];
    const float* Pb = P + ((size_t)b * O + o) * NPTS;
    const float* Sb = S + ((size_t)b * O + o) * NPTS;
    const int*   ib = idx + (size_t)b * MBIG;
    for (int j = t; j < NPTS; j += 256) prow[j] = Pb[j];
    __syncthreads();
    double s1 = 0.0, s2 = 0.0;
    for (int n = t; n < NPTS; n += 256) {
        float sv = Sb[n];
        const int* ii = ib + n * KNN;
        float ts = 0.f, us = 0.f;
        #pragma unroll
        for (int k = 0; k < KNN; k++) {
            float p = prow[ii[k]];
            ts += p;
            us = fmaf(p, p, us);
        }
        s1 += (double)(ts + 10.f * sv);
        s2 += (double)(us + 2.f * sv * ts + 10.f * sv * sv);
    }
    r1[t] = s1; r2[t] = s2;
    __syncthreads();
    for (int w = 128; w > 0; w >>= 1) {
        if (t < w) { r1[t] += r1[t + w]; r2[t] += r2[t + w]; }
        __syncthreads();
    }
    if (t == 0) { p1[o * BSZ + b] = r1[0]; p2[o * BSZ + b] = r2[0]; }
}

// --- stage 2: deterministic finalize (ascending b) -> BN affine a/bb --------
__global__ void stats_ps_final_k(const double* __restrict__ p1, const double* __restrict__ p2,
                                 const float* __restrict__ gam, const float* __restrict__ bet,
                                 float* __restrict__ Aout, float* __restrict__ BBout, int O)
{
    int o = blockIdx.x * blockDim.x + threadIdx.x;
    if (o >= O) return;
    double s1 = 0.0, s2 = 0.0;
    #pragma unroll
    for (int b = 0; b < BSZ; b++) { s1 += p1[o * BSZ + b]; s2 += p2[o * BSZ + b]; }
    double inv = 1.0 / ((double)BSZ * (double)MBIG);
    double mu  = s1 * inv;
    double var = s2 * inv - mu * mu;
    if (var < 0.0) var = 0.0;
    float a  = rsqrtf((float)var + 1e-5f) * gam[o];
    float bb = bet[o] - (float)mu * a;
    Aout[o]  = a;
    BBout[o] = bb;
}

// -------- combine + BN affine + leaky: Y1 = leaky(a*(P[idx]+S) + bb) --------
__global__ void combine_bn_k(const float* __restrict__ P, const float* __restrict__ S,
                             const int* __restrict__ idx,
                             const float* __restrict__ A, const float* __restrict__ BB,
                             float* __restrict__ Y, int O)
{
    size_t total = (size_t)BSZ * O * MBIG;
    size_t i = (size_t)blockIdx.x * blockDim.x + threadIdx.x;
    if (i >= total) return;
    int m = (int)(i % MBIG);
    size_t r = i / MBIG;
    int o = (int)(r % O);
    int b = (int)(r / O);
    int n = m / KNN;
    int j = idx[(size_t)b * MBIG + m];
    size_t base = ((size_t)b * O + o) * NPTS;
    float v = fmaf(P[base + j] + S[base + n], A[o], BB[o]);
    Y[i] = (v >= 0.f) ? v : 0.2f * v;
}

// ------- BN statistics, two-pass (BIT-FROZEN: block-1 stats feed knn-2) ------
__global__ void bn_stats_k(const float* __restrict__ Y, float* __restrict__ mean,
                           float* __restrict__ var, int O, int M)
{
    const int c = blockIdx.x;
    const int t = threadIdx.x;
    __shared__ float ss[256];
    __shared__ float mu_s;
    float s = 0.f;
    for (int b = 0; b < BSZ; b++) {
        const float* p = Y + ((size_t)b * O + c) * M;
        for (int m = t; m < M; m += 256) s += p[m];
    }
    ss[t] = s;
    __syncthreads();
    for (int w = 128; w > 0; w >>= 1) {
        if (t < w) ss[t] += ss[t + w];
        __syncthreads();
    }
    if (t == 0) {
        float mu = ss[0] / ((float)BSZ * (float)M);
        mean[c] = mu;
        mu_s = mu;
    }
    __syncthreads();
    const float mu = mu_s;
    float s2 = 0.f;
    for (int b = 0; b < BSZ; b++) {
        const float* p = Y + ((size_t)b * O + c) * M;
        for (int m = t; m < M; m += 256) { float d = p[m] - mu; s2 += d * d; }
    }
    ss[t] = s2;
    __syncthreads();
    for (int w = 128; w > 0; w >>= 1) {
        if (t < w) ss[t] += ss[t + w];
        __syncthreads();
    }
    if (t == 0) var[c] = ss[0] / ((float)BSZ * (float)M);
}

// ------- BN statistics, single-pass (tolerance paths) ----------
__global__ void bn_stats_fast_k(const float* __restrict__ Y, float* __restrict__ mean,
                                float* __restrict__ var, int O, int M)
{
    const int c = blockIdx.x;
    const int t = threadIdx.x;
    __shared__ float ss[256], ss2[256];
    float s = 0.f, s2 = 0.f;
    for (int b = 0; b < BSZ; b++) {
        const float* p = Y + ((size_t)b * O + c) * M;
        for (int m = t * 4; m < M; m += 1024) {
            float4 v = *(const float4*)(p + m);
            s += v.x; s2 = fmaf(v.x, v.x, s2);
            s += v.y; s2 = fmaf(v.y, v.y, s2);
            s += v.z; s2 = fmaf(v.z, v.z, s2);
            s += v.w; s2 = fmaf(v.w, v.w, s2);
        }
    }
    ss[t] = s; ss2[t] = s2;
    __syncthreads();
    for (int w = 128; w > 0; w >>= 1) {
        if (t < w) { ss[t] += ss[t + w]; ss2[t] += ss2[t + w]; }
        __syncthreads();
    }
    if (t == 0) {
        float inv = 1.f / ((float)BSZ * (float)M);
        float mu  = ss[0] * inv;
        mean[c] = mu;
        var[c]  = fmaxf(ss2[0] * inv - mu * mu, 0.f);
    }
}

// -------- apply BN affine + leaky relu, in place ----
__global__ void bn_leaky_k(float* __restrict__ Y, const float* __restrict__ mean,
                           const float* __restrict__ var, const float* __restrict__ gam,
                           const float* __restrict__ bet, int O, size_t M)
{
    size_t total = (size_t)BSZ * O * M;
    size_t i = ((size_t)blockIdx.x * blockDim.x + threadIdx.x) * 4;
    if (i >= total) return;
    int c = (int)((i / M) % O);
    float a  = rsqrtf(var[c] + 1e-5f) * gam[c];
    float bb = bet[c] - mean[c] * a;
    float4 v = *(float4*)(Y + i);
    float tt;
    tt = fmaf(v.x, a, bb); v.x = (tt >= 0.f) ? tt : 0.2f * tt;
    tt = fmaf(v.y, a, bb); v.y = (tt >= 0.f) ? tt : 0.2f * tt;
    tt = fmaf(v.z, a, bb); v.z = (tt >= 0.f) ? tt : 0.2f * tt;
    tt = fmaf(v.w, a, bb); v.w = (tt >= 0.f) ? tt : 0.2f * tt;
    *(float4*)(Y + i) = v;
}

// ---- BN + leaky + max over K, exact ref op order (BIT-FROZEN) ----
__global__ void bn_leaky_maxk_k(const float* __restrict__ Y, const float* __restrict__ mean,
                                const float* __restrict__ var, const float* __restrict__ gam,
                                const float* __restrict__ bet, float* __restrict__ out, int O)
{
    size_t total = (size_t)BSZ * O * NPTS;
    size_t i = (size_t)blockIdx.x * blockDim.x + threadIdx.x;
    if (i >= total) return;
    int n = (int)(i % NPTS);
    int c = (int)((i / NPTS) % O);
    int b = (int)(i / ((size_t)NPTS * O));
    const float mu = mean[c];
    const float s  = __fsqrt_rn(__fadd_rn(var[c], 1e-5f));
    const float g  = gam[c];
    const float be = bet[c];
    const float* p = Y + ((size_t)b * O + c) * MBIG + (size_t)n * KNN;
    float sel = p[0];
    if (g >= 0.f) {
        #pragma unroll
        for (int k = 1; k < KNN; k++) sel = fmaxf(sel, p[k]);
    } else {
        #pragma unroll
        for (int k = 1; k < KNN; k++) sel = fminf(sel, p[k]);
    }
    float t = __fdiv_rn(__fsub_rn(sel, mu), s);
    t = __fadd_rn(__fmul_rn(t, g), be);
    t = (t >= 0.f) ? t : __fmul_rn(0.2f, t);
    out[i] = t;
}

// ============================ host launcher ============================
static inline void* symaddr(const void* sym)
{
    void* p = nullptr;
    cudaGetSymbolAddress(&p, sym);
    return p;
}

extern "C" void kernel_launch(void* const* d_in, const int* in_sizes, int n_in,
                              void* d_out, int out_size)
{
    (void)in_sizes; (void)n_in; (void)out_size;
    const float* x = (const float*)d_in[0];

    const float* P24[24];
    for (int i = 0; i < 24; i++) P24[i] = (const float*)d_in[1 + i];
    #define W1(p)  P24[(p)*8 + 0]
    #define B1(p)  P24[(p)*8 + 1]
    #define G1(p)  P24[(p)*8 + 2]
    #define BE1(p) P24[(p)*8 + 3]
    #define W2(p)  P24[(p)*8 + 4]
    #define B2(p)  P24[(p)*8 + 5]
    #define G2(p)  P24[(p)*8 + 6]
    #define BE2(p) P24[(p)*8 + 7]

    float* G    = (float*)symaddr(g_G);
    float* SQ   = (float*)symaddr(g_sq);
    int*   IDX  = (int*)  symaddr(g_idx);
    float* FEAT = (float*)symaddr(g_feat);
    float* Y1   = (float*)symaddr(g_y1);
    float* Y2   = (float*)symaddr(g_y2);
    float* X1   = (float*)symaddr(g_x1);
    float* X2   = (float*)symaddr(g_x2);
    float* Y3   = (float*)symaddr(g_y3);
    float* PP   = (float*)symaddr(g_P);
    float* SS   = (float*)symaddr(g_S);
    float* WT   = (float*)symaddr(g_wt);
    double* P1  = (double*)symaddr(g_p1);
    double* P2  = (double*)symaddr(g_p2);
    float* MEAN = (float*)symaddr(g_mean);
    float* VAR  = (float*)symaddr(g_var);
    float* OUT  = (float*)d_out;

    const int ew = 256;
    #define GS(total) (unsigned)(((total) + ew - 1) / ew)
    #define CT(C) (((C) + KT - 1) & ~(KT - 1))

    auto conv = [&](const float* W, const float* bias, const float* Xin, float* Yout,
                    int O, int C, int M) {
        transw_k<<<GS(CT(C) * OPAD), ew>>>(W, WT, O, C, C, 0);
        gemm_db_k<<<dim3(M / 128, (O + 127) / 128, BSZ), 256>>>(
            WT, Xin, bias, Yout, O, C, M, OPAD, 0, (size_t)C * M, (size_t)O * M);
    };

    auto knn = [&](const float* xin, int C) {
        sqnorm_warp_k<<<(BSZ * NPTS * 32 + 255) / 256, 256>>>(xin, SQ, C);
        // gram: upper-triangle blocks only, then bit-exact mirror
        gemm_tri_k<<<dim3(NPTS / 128, NPTS / 128, BSZ), 256>>>(
            xin, xin, G, C, (size_t)C * NPTS, (size_t)NPTS * NPTS);
        mirror_k<<<dim3(NPTS / 128, NPTS / 128, BSZ), 256>>>(G);
        topk_k<<<dim3(NPTS, BSZ), 256>>>(G, SQ, IDX);
    };

    // ================= block 1 (FROZEN path: produces x1 -> knn-2) ============
    {
        const int C = 64, O1 = 152, O2 = 181;
        knn(x, C);
        gather_k<<<GS((size_t)BSZ * 2 * C * MBIG), ew>>>(x, IDX, FEAT, C);
        conv(W1(0), B1(0), FEAT, Y1, O1, 2 * C, MBIG);
        bn_stats_k<<<O1, 256>>>(Y1, MEAN, VAR, O1, MBIG);
        bn_leaky_k<<<GS((size_t)BSZ * O1 * MBIG / 4), ew>>>(Y1, MEAN, VAR, G1(0), BE1(0), O1, MBIG);
        conv(W2(0), B2(0), Y1, Y2, O2, O1, MBIG);
        bn_stats_k<<<O2, 256>>>(Y2, MEAN, VAR, O2, MBIG);
        bn_leaky_maxk_k<<<GS((size_t)BSZ * O2 * NPTS), ew>>>(Y2, MEAN, VAR, G2(0), BE2(0), X1, O2);
    }

    // ====== block 2 (tolerance path: split conv1 + parallel analytic stats) ==
    {
        const int C = 181, O1 = 430, O2 = 512;
        knn(X1, C);
        transw_k<<<GS(CT(C) * OPAD), ew>>>(W1(1), WT, O1, C, 2 * C, 0);
        gemm_db_k<<<dim3(NPTS / 128, (O1 + 127) / 128, BSZ), 256>>>(
            WT, X1, nullptr, PP, O1, C, NPTS, OPAD, 0, (size_t)C * NPTS, (size_t)O1 * NPTS);
        transw_diff_k<<<GS(CT(C) * OPAD), ew>>>(W1(1), WT, O1, C, 2 * C, 0, C);
        gemm_db_k<<<dim3(NPTS / 128, (O1 + 127) / 128, BSZ), 256>>>(
            WT, X1, B1(1), SS, O1, C, NPTS, OPAD, 0, (size_t)C * NPTS, (size_t)O1 * NPTS);
        stats_ps_part_k<<<dim3(O1, BSZ), 256>>>(PP, SS, IDX, P1, P2, O1);
        stats_ps_final_k<<<(O1 + 255) / 256, 256>>>(P1, P2, G1(1), BE1(1), MEAN, VAR, O1);
        combine_bn_k<<<GS((size_t)BSZ * O1 * MBIG), ew>>>(PP, SS, IDX, MEAN, VAR, Y1, O1);
        conv(W2(1), B2(1), Y1, Y2, O2, O1, MBIG);
        bn_stats_fast_k<<<O2, 256>>>(Y2, MEAN, VAR, O2, MBIG);
        bn_leaky_maxk_k<<<GS((size_t)BSZ * O2 * NPTS), ew>>>(Y2, MEAN, VAR, G2(1), BE2(1), X2, O2);
    }

    // ====== block 3 (tolerance path; concat fused into dual-source GEMM) =====
    {
        const int C = 693, Csplit = 181, O1 = 595, O2 = 512;
        transw_k<<<GS(CT(C) * OPAD), ew>>>(W1(2), WT, O1, C, C, 0);
        gemm_db_dual_k<<<dim3(NPTS / 128, (O1 + 127) / 128, BSZ), 256>>>(
            WT, X1, X2, Csplit, B1(2), Y3, O1, C, NPTS, OPAD,
            0, (size_t)Csplit * NPTS, (size_t)512 * NPTS, (size_t)O1 * NPTS);
        bn_stats_fast_k<<<O1, 256>>>(Y3, MEAN, VAR, O1, NPTS);
        bn_leaky_k<<<GS((size_t)BSZ * O1 * NPTS / 4), ew>>>(Y3, MEAN, VAR, G1(2), BE1(2), O1, NPTS);
        conv(W2(2), B2(2), Y3, OUT, O2, O1, NPTS);
        bn_stats_fast_k<<<O2, 256>>>(OUT, MEAN, VAR, O2, NPTS);
        bn_leaky_k<<<GS((size_t)BSZ * O2 * NPTS / 4), ew>>>(OUT, MEAN, VAR, G2(2), BE2(2), O2, NPTS);
    }
}